// round 1
// baseline (speedup 1.0000x reference)
#include <cuda_runtime.h>

// Problem constants
#define BB    8
#define CI_N  512
#define CO_N  512
#define HH    64
#define WW    64
#define HWN   4096
#define NCLS  35
#define SDIM  512

// ---------------- scratch (device globals: no runtime allocation) ----------------
__device__ float g_s[BB * CI_N];            // style modulation per (b, ci)
__device__ float g_cwT[CO_N * NCLS];        // CLADE weight, transposed [co][cls]
__device__ float g_cbT[CO_N * NCLS];        // CLADE bias,  transposed [co][cls]
__device__ float g_conv[(size_t)BB * CO_N * HWN]; // conv output scratch (64 MB)
__device__ float g_mean[BB * CO_N];
__device__ float g_rstd[BB * CO_N];

// ---------------- packed f32x2 helpers ----------------
__device__ __forceinline__ unsigned long long pk2(float lo, float hi) {
    unsigned long long r;
    asm("mov.b64 %0, {%1, %2};" : "=l"(r) : "f"(lo), "f"(hi));
    return r;
}
__device__ __forceinline__ void fma2(unsigned long long& d,
                                     unsigned long long a,
                                     unsigned long long b) {
    asm("fma.rn.f32x2 %0, %1, %2, %0;" : "+l"(d) : "l"(a), "l"(b));
}

// ---------------- EqualLinear: out = (X @ W^T)/sqrt(SDIM) + bias ----------------
// which: 0 -> g_s (dst[j + i*512]), 1 -> g_cwT (dst[j*35 + i]), 2 -> g_cbT
__global__ void eqlin_kernel(const float* __restrict__ X,
                             const float* __restrict__ W,
                             const float* __restrict__ bias,
                             int M, int N, int sj, int si, int which)
{
    int wg   = (blockIdx.x * blockDim.x + threadIdx.x) >> 5;
    int lane = threadIdx.x & 31;
    if (wg >= M * N) return;
    int i = wg / N;
    int j = wg - i * N;

    const float4* x4 = (const float4*)(X + (size_t)i * SDIM);
    const float4* w4 = (const float4*)(W + (size_t)j * SDIM);
    float acc = 0.f;
#pragma unroll
    for (int q = 0; q < 4; q++) {
        float4 a = x4[lane + q * 32];
        float4 b = w4[lane + q * 32];
        acc += a.x * b.x + a.y * b.y + a.z * b.z + a.w * b.w;
    }
#pragma unroll
    for (int o = 16; o > 0; o >>= 1) acc += __shfl_xor_sync(0xffffffffu, acc, o);

    if (lane == 0) {
        float v = acc * 0.04419417382415922f + bias[j];  // 1/sqrt(512)
        float* dst = (which == 0) ? g_s : (which == 1) ? g_cwT : g_cbT;
        dst[j * sj + i * si] = v;
    }
}

// ---------------- Conv 3x3 (shared weight, per-channel input scaling fused) ----------------
// Block: 64 co x 256 px (16x16 spatial tile). Thread: 8 co x 8 px (4 f32x2 pairs).
__global__ void __launch_bounds__(256, 2)
conv_kernel(const float* __restrict__ x, const float* __restrict__ wgt)
{
    __shared__ float xs[8 * 18 * 19];   // [ci][row 18][col 18, pitch 19]
    __shared__ float ws[8 * 9 * 64];    // [(ci*9 + k) * 64 + co]

    const int b   = blockIdx.z;
    const int co0 = blockIdx.y * 64;
    const int tr  = (blockIdx.x >> 2) * 16;   // tile row origin
    const int tc  = (blockIdx.x & 3) * 16;    // tile col origin
    const int tid = threadIdx.x;
    const int warp = tid >> 5;
    const int lane = tid & 31;
    const int co_off = warp * 8;              // 8 co per thread
    const int pr = lane >> 1;                 // 16 pixel rows
    const int pc = (lane & 1) * 8;            // 2 groups of 8 cols

    unsigned long long acc[8][4];
#pragma unroll
    for (int i = 0; i < 8; i++)
#pragma unroll
        for (int p = 0; p < 4; p++) acc[i][p] = 0ull;

    const float* xb = x + (size_t)b * CI_N * HWN;
    const float* sb = g_s + b * CI_N;

    for (int it = 0; it < 64; ++it) {
        const int ci0 = it * 8;

        // load 64co x 8ci x 9 weights: per co the 72 floats are contiguous in global
#pragma unroll
        for (int l = 0; l < 18; l++) {
            int idx = tid + l * 256;          // 0..4607
            int co  = idx / 72;
            int r   = idx - co * 72;
            int ci  = r / 9;
            int k   = r - ci * 9;
            ws[(ci * 9 + k) * 64 + co] =
                wgt[((size_t)(co0 + co) * CI_N + (ci0 + ci)) * 9 + k];
        }
        // load 8ci x 18x18 input tile with halo, scaled by s[b,ci]
        for (int idx = tid; idx < 8 * 18 * 18; idx += 256) {
            int ci = idx / 324;
            int r2 = idx - ci * 324;
            int rr = r2 / 18;
            int cc = r2 - rr * 18;
            int gr = tr - 1 + rr;
            int gc = tc - 1 + cc;
            float v = 0.f;
            if ((unsigned)gr < 64u && (unsigned)gc < 64u)
                v = xb[(size_t)(ci0 + ci) * HWN + gr * 64 + gc] * sb[ci0 + ci];
            xs[ci * 342 + rr * 19 + cc] = v;
        }
        __syncthreads();

#pragma unroll 1
        for (int ci = 0; ci < 8; ++ci) {
#pragma unroll
            for (int ky = 0; ky < 3; ++ky) {
                const float* xr = &xs[ci * 342 + (pr + ky) * 19 + pc];
                float xrow[10];
#pragma unroll
                for (int j = 0; j < 10; j++) xrow[j] = xr[j];
                unsigned long long A[5], O[4];
#pragma unroll
                for (int p = 0; p < 5; p++) A[p] = pk2(xrow[2 * p], xrow[2 * p + 1]);
#pragma unroll
                for (int p = 0; p < 4; p++) O[p] = pk2(xrow[2 * p + 1], xrow[2 * p + 2]);

                const float* wr = &ws[(ci * 9 + ky * 3) * 64 + co_off];
#pragma unroll
                for (int co = 0; co < 8; ++co) {
                    float w0 = wr[co], w1 = wr[64 + co], w2 = wr[128 + co];
                    unsigned long long W0 = pk2(w0, w0);
                    unsigned long long W1 = pk2(w1, w1);
                    unsigned long long W2 = pk2(w2, w2);
#pragma unroll
                    for (int p = 0; p < 4; p++) {
                        fma2(acc[co][p], W0, A[p]);
                        fma2(acc[co][p], W1, O[p]);
                        fma2(acc[co][p], W2, A[p + 1]);
                    }
                }
            }
        }
        __syncthreads();
    }

    // epilogue: write conv result (pre-norm) to scratch
    const int orow = tr + pr;
    const int ocol = tc + pc;
#pragma unroll
    for (int co = 0; co < 8; co++) {
        float2* o = (float2*)&g_conv[(size_t)(b * CO_N + co0 + co_off + co) * HWN +
                                     orow * 64 + ocol];
#pragma unroll
        for (int p = 0; p < 4; p++) {
            union { unsigned long long u; float2 f; } cv;
            cv.u = acc[co][p];
            o[p] = cv.f;
        }
    }
}

// ---------------- Instance-norm statistics per (b, co) ----------------
__global__ void stats_kernel()
{
    const int bc = blockIdx.x;                 // 0 .. 4095
    const float4* p = (const float4*)(g_conv + (size_t)bc * HWN);
    const int t = threadIdx.x;
    float s1 = 0.f, s2 = 0.f;
#pragma unroll
    for (int q = 0; q < 4; q++) {
        float4 v = p[t + q * 256];
        s1 += v.x + v.y + v.z + v.w;
        s2 += v.x * v.x + v.y * v.y + v.z * v.z + v.w * v.w;
    }
#pragma unroll
    for (int o = 16; o > 0; o >>= 1) {
        s1 += __shfl_xor_sync(0xffffffffu, s1, o);
        s2 += __shfl_xor_sync(0xffffffffu, s2, o);
    }
    __shared__ float r1[8], r2[8];
    if ((t & 31) == 0) { r1[t >> 5] = s1; r2[t >> 5] = s2; }
    __syncthreads();
    if (t < 8) {
        s1 = r1[t];
        s2 = r2[t];
#pragma unroll
        for (int o = 4; o > 0; o >>= 1) {
            s1 += __shfl_xor_sync(0xffu, s1, o);
            s2 += __shfl_xor_sync(0xffu, s2, o);
        }
        if (t == 0) {
            float m   = s1 * (1.f / 4096.f);
            float var = s2 * (1.f / 4096.f) - m * m;
            g_mean[bc] = m;
            g_rstd[bc] = rsqrtf(var + 1e-5f);
        }
    }
}

// ---------------- Normalize + CLADE affine via label gather ----------------
__global__ void apply_kernel(const int* __restrict__ label, float* __restrict__ out)
{
    const int idx = blockIdx.x * 256 + threadIdx.x;  // over 8*512*1024 float4 groups
    const int b   = idx >> 19;                       // / (512*1024)
    const int rem = idx & 524287;
    const int co  = rem >> 10;
    const int hw4 = rem & 1023;

    float4 cv = ((const float4*)g_conv)[idx];
    int4  lb  = ((const int4*)label)[b * 1024 + hw4];
    const float m  = g_mean[b * CO_N + co];
    const float rs = g_rstd[b * CO_N + co];
    const float* cw = g_cwT + co * NCLS;
    const float* cb = g_cbT + co * NCLS;

    float4 o;
    o.x = (cv.x - m) * rs * cw[lb.x] + cb[lb.x];
    o.y = (cv.y - m) * rs * cw[lb.y] + cb[lb.y];
    o.z = (cv.z - m) * rs * cw[lb.z] + cb[lb.z];
    o.w = (cv.w - m) * rs * cw[lb.w] + cb[lb.w];
    ((float4*)out)[idx] = o;
}

// ---------------- launch ----------------
extern "C" void kernel_launch(void* const* d_in, const int* in_sizes, int n_in,
                              void* d_out, int out_size)
{
    const float* input       = (const float*)d_in[0];
    const float* style       = (const float*)d_in[1];
    const float* class_style = (const float*)d_in[2];
    const float* weight      = (const float*)d_in[3];
    const float* mod_w       = (const float*)d_in[4];
    const float* mod_b       = (const float*)d_in[5];
    const float* cw_w        = (const float*)d_in[6];
    const float* cw_b        = (const float*)d_in[7];
    const float* cb_w        = (const float*)d_in[8];
    const float* cb_b        = (const float*)d_in[9];
    const int*   label       = (const int*)d_in[10];
    float* out = (float*)d_out;

    // s[b,ci] = style @ mod_w^T / sqrt(512) + 1
    eqlin_kernel<<<(BB * CI_N + 7) / 8, 256>>>(style, mod_w, mod_b,
                                               BB, CI_N, 1, CI_N, 0);
    // CLADE tables, transposed to [co][cls] for fast gather
    eqlin_kernel<<<(NCLS * CO_N + 7) / 8, 256>>>(class_style, cw_w, cw_b,
                                                 NCLS, CO_N, NCLS, 1, 1);
    eqlin_kernel<<<(NCLS * CO_N + 7) / 8, 256>>>(class_style, cb_w, cb_b,
                                                 NCLS, CO_N, NCLS, 1, 2);

    dim3 grid(16, 8, 8);   // 16 spatial tiles, 8 co tiles, 8 batch
    conv_kernel<<<grid, 256>>>(input, weight);

    stats_kernel<<<BB * CO_N, 256>>>();
    apply_kernel<<<(BB * CO_N * HWN) / 4 / 256, 256>>>(label, out);
}

// round 3
// speedup vs baseline: 6.6442x; 6.6442x over previous
#include <cuda_runtime.h>
#include <cstdint>

// Problem constants
#define BB    8
#define CI_N  512
#define CO_N  512
#define HWN   4096
#define NCLS  35
#define SDIM  512

// conv smem geometry
#define XPITCH 76
#define XCISTR (6 * XPITCH)          // 456 floats per ci slab
#define XBUFB  (8 * XCISTR * 4)      // 14592 B per X buffer
#define WBUFB  18432                 // 4 co_sub * 9 tap * 128 floats * 4B
#define SMEMB  (2 * XBUFB + 2 * WBUFB)   // 66048 B

// ---------------- scratch (device globals) ----------------
__device__ float g_s[BB * CI_N];
__device__ float g_cwT[CO_N * NCLS];
__device__ float g_cbT[CO_N * NCLS];
__device__ float g_wA[(size_t)9 * CO_N * CI_N];      // fragment-ordered weights
__device__ float g_xs[(size_t)BB * CI_N * HWN];      // tf32(x * s)
__device__ float g_conv[(size_t)BB * CO_N * HWN];
__device__ float g_mean[BB * CO_N];
__device__ float g_rstd[BB * CO_N];

// ---------------- helpers ----------------
__device__ __forceinline__ uint32_t smem_u32(const void* p) {
    uint32_t a;
    asm("{ .reg .u64 t; cvta.to.shared.u64 t, %1; cvt.u32.u64 %0, t; }" : "=r"(a) : "l"(p));
    return a;
}
__device__ __forceinline__ void cp_async16(uint32_t dst, const void* src) {
    asm volatile("cp.async.cg.shared.global [%0], [%1], 16;" :: "r"(dst), "l"(src) : "memory");
}
#define CP_COMMIT() asm volatile("cp.async.commit_group;" ::: "memory")
#define CP_WAIT(n)  asm volatile("cp.async.wait_group %0;" :: "n"(n) : "memory")
#define STS_ZERO4(a) asm volatile("st.shared.v4.b32 [%0], {%1,%1,%1,%1};" :: "r"(a), "r"(0) : "memory")

__device__ __forceinline__ uint32_t cvt_tf32(float v) {
    uint32_t t;
    asm("cvt.rna.tf32.f32 %0, %1;" : "=r"(t) : "f"(v));
    return t;
}
__device__ __forceinline__ void mma8(float* c, uint4 a, uint32_t b0, uint32_t b1) {
    asm volatile(
        "mma.sync.aligned.m16n8k8.row.col.f32.tf32.tf32.f32 "
        "{%0,%1,%2,%3}, {%4,%5,%6,%7}, {%8,%9}, {%0,%1,%2,%3};"
        : "+f"(c[0]), "+f"(c[1]), "+f"(c[2]), "+f"(c[3])
        : "r"(a.x), "r"(a.y), "r"(a.z), "r"(a.w), "r"(b0), "r"(b1));
}

// ---------------- EqualLinear ----------------
__global__ void eqlin_kernel(const float* __restrict__ X, const float* __restrict__ W,
                             const float* __restrict__ bias,
                             int M, int N, int sj, int si, int which)
{
    int wg = (blockIdx.x * blockDim.x + threadIdx.x) >> 5;
    int lane = threadIdx.x & 31;
    if (wg >= M * N) return;
    int i = wg / N, j = wg - i * N;
    const float4* x4 = (const float4*)(X + (size_t)i * SDIM);
    const float4* w4 = (const float4*)(W + (size_t)j * SDIM);
    float acc = 0.f;
#pragma unroll
    for (int q = 0; q < 4; q++) {
        float4 a = x4[lane + q * 32], b = w4[lane + q * 32];
        acc += a.x * b.x + a.y * b.y + a.z * b.z + a.w * b.w;
    }
#pragma unroll
    for (int o = 16; o > 0; o >>= 1) acc += __shfl_xor_sync(0xffffffffu, acc, o);
    if (lane == 0) {
        float v = acc * 0.04419417382415922f + bias[j];
        float* dst = (which == 0) ? g_s : (which == 1) ? g_cwT : g_cbT;
        dst[j * sj + i * si] = v;
    }
}

// ---------------- weight -> A-fragment order, tf32-rounded ----------------
// g_wA[((co_blk*64 + ci_blk)*9 + tap)*128 + lane*4 + j]
//   co = co_blk*16 + (lane>>2) + (j&1)*8 ; ci = ci_blk*8 + (lane&3) + ((j>>1)&1)*4
__global__ void wfrag_kernel(const float* __restrict__ w)
{
    int idx = blockIdx.x * 256 + threadIdx.x;
    if (idx >= 9 * CO_N * CI_N) return;
    int j = idx & 3;
    int l = (idx >> 2) & 31;
    int tap = (idx >> 7) % 9;
    int cib = (idx / 1152) % 64;
    int cob = idx / 73728;
    int co = cob * 16 + (l >> 2) + (j & 1) * 8;
    int ci = cib * 8 + (l & 3) + ((j >> 1) & 1) * 4;
    float v = w[((size_t)co * CI_N + ci) * 9 + tap];
    g_wA[idx] = __uint_as_float(cvt_tf32(v));
}

// ---------------- x * s -> tf32 ----------------
__global__ void xscale_kernel(const float* __restrict__ x)
{
    int idx = blockIdx.x * 256 + threadIdx.x;          // float4 units
    int b = idx >> 19;
    int ci = (idx >> 10) & 511;
    float s = g_s[b * CI_N + ci];
    float4 v = ((const float4*)x)[idx];
    uint4 o;
    o.x = cvt_tf32(v.x * s);
    o.y = cvt_tf32(v.y * s);
    o.z = cvt_tf32(v.z * s);
    o.w = cvt_tf32(v.w * s);
    ((uint4*)g_xs)[idx] = o;
}

// ---------------- conv: implicit GEMM via mma.sync tf32 ----------------
__device__ __forceinline__ void stage(char* sm, int buf, int c,
                                      const float* xsrc, const float* wsrc,
                                      int r0, int tid)
{
    // X: 8 ci x 6 rows x 64 cols -> 768 x 16B
    uint32_t xb = smem_u32(sm) + buf * XBUFB;
#pragma unroll
    for (int k = 0; k < 3; k++) {
        int idx = tid + k * 256;
        int ci = idx / 96;
        int rem = idx - ci * 96;
        int srow = rem >> 4;
        int q = rem & 15;
        uint32_t dst = xb + (uint32_t)ci * (XCISTR * 4) + srow * (XPITCH * 4) + 16 + q * 16;
        int gr = r0 - 1 + srow;
        if ((unsigned)gr < 64u)
            cp_async16(dst, xsrc + (size_t)(c * 8 + ci) * HWN + gr * 64 + q * 4);
        else
            STS_ZERO4(dst);
    }
    // W: 4 co_sub x 1152 floats -> 1152 x 16B
    uint32_t wb = smem_u32(sm) + 2 * XBUFB + buf * WBUFB;
#pragma unroll
    for (int k = 0; k < 4; k++) {
        int idx = tid + k * 256;
        int cs = idx / 288;
        int r = idx - cs * 288;
        cp_async16(wb + cs * 4608 + r * 16,
                   wsrc + ((size_t)cs * 64 + c) * 1152 + r * 4);
    }
    if (tid < 128) {
        int idx = 1024 + tid;
        int cs = idx / 288;
        int r = idx - cs * 288;
        cp_async16(wb + cs * 4608 + r * 16,
                   wsrc + ((size_t)cs * 64 + c) * 1152 + r * 4);
    }
}

__global__ void __launch_bounds__(256, 2) conv_mma_kernel()
{
    extern __shared__ char sm[];
    const int tid = threadIdx.x;
    const int bx = blockIdx.x;
    const int rb = bx & 15, cb = (bx >> 4) & 7, b = bx >> 7;
    const int r0 = rb * 4, co0 = cb * 64;
    const int wid = tid >> 5, lane = tid & 31;
    const int wco = wid & 1, wrow = wid >> 1;
    const int g = lane >> 2, t = lane & 3;

    const float* xsrc = g_xs + (size_t)b * CI_N * HWN;
    const float* wsrc = g_wA + (size_t)(cb * 4) * 64 * 1152;

    // zero halo columns (float slots 3 and 68 of each row), both buffers
    if (tid < 96) {
        int bufz = tid / 48;
        int rr = tid - bufz * 48;
        int ci = rr / 6, srow = rr - ci * 6;
        float* rbase = (float*)(sm + bufz * XBUFB) + ci * XCISTR + srow * XPITCH;
        rbase[3] = 0.f;
        rbase[68] = 0.f;
    }

    float C[2][8][4];
#pragma unroll
    for (int m = 0; m < 2; m++)
#pragma unroll
        for (int tn = 0; tn < 8; tn++)
#pragma unroll
            for (int j = 0; j < 4; j++) C[m][tn][j] = 0.f;

    stage(sm, 0, 0, xsrc, wsrc, r0, tid); CP_COMMIT();
    stage(sm, 1, 1, xsrc, wsrc, r0, tid); CP_COMMIT();

    for (int c = 0; c < 64; c++) {
        const int buf = c & 1;
        CP_WAIT(1);
        __syncthreads();
        const uint4* wbb = (const uint4*)(sm + 2 * XBUFB + buf * WBUFB);
        const uint32_t* xbb = (const uint32_t*)(sm + buf * XBUFB);
#pragma unroll
        for (int ky = 0; ky < 3; ky++) {
#pragma unroll
            for (int kx = 0; kx < 3; kx++) {
                const int tap = ky * 3 + kx;
                uint4 A0 = wbb[(2 * wco + 0) * 288 + tap * 32 + lane];
                uint4 A1 = wbb[(2 * wco + 1) * 288 + tap * 32 + lane];
                const uint32_t* xr = xbb + t * XCISTR + (wrow + ky) * XPITCH + 3 + g + kx;
#pragma unroll
                for (int tn = 0; tn < 8; tn++) {
                    uint32_t b0 = xr[tn * 8];
                    uint32_t b1 = xr[tn * 8 + 4 * XCISTR];
                    mma8(C[0][tn], A0, b0, b1);
                    mma8(C[1][tn], A1, b0, b1);
                }
            }
        }
        __syncthreads();
        if (c + 2 < 64) stage(sm, buf, c + 2, xsrc, wsrc, r0, tid);
        CP_COMMIT();
    }

    // epilogue
    const int row = r0 + wrow;
#pragma unroll
    for (int m = 0; m < 2; m++) {
        int co = co0 + wco * 32 + m * 16 + g;
        float* base0 = g_conv + ((size_t)(b * CO_N + co)) * HWN + row * 64;
#pragma unroll
        for (int tn = 0; tn < 8; tn++) {
            int col = tn * 8 + 2 * t;
            *(float2*)(base0 + col) = make_float2(C[m][tn][0], C[m][tn][1]);
            *(float2*)(base0 + (size_t)8 * HWN + col) = make_float2(C[m][tn][2], C[m][tn][3]);
        }
    }
}

// ---------------- Instance-norm statistics ----------------
__global__ void stats_kernel()
{
    const int bc = blockIdx.x;
    const float4* p = (const float4*)(g_conv + (size_t)bc * HWN);
    const int t = threadIdx.x;
    float s1 = 0.f, s2 = 0.f;
#pragma unroll
    for (int q = 0; q < 4; q++) {
        float4 v = p[t + q * 256];
        s1 += v.x + v.y + v.z + v.w;
        s2 += v.x * v.x + v.y * v.y + v.z * v.z + v.w * v.w;
    }
#pragma unroll
    for (int o = 16; o > 0; o >>= 1) {
        s1 += __shfl_xor_sync(0xffffffffu, s1, o);
        s2 += __shfl_xor_sync(0xffffffffu, s2, o);
    }
    __shared__ float r1[8], r2[8];
    if ((t & 31) == 0) { r1[t >> 5] = s1; r2[t >> 5] = s2; }
    __syncthreads();
    if (t < 8) {
        s1 = r1[t]; s2 = r2[t];
#pragma unroll
        for (int o = 4; o > 0; o >>= 1) {
            s1 += __shfl_xor_sync(0xffu, s1, o);
            s2 += __shfl_xor_sync(0xffu, s2, o);
        }
        if (t == 0) {
            float m = s1 * (1.f / 4096.f);
            float var = s2 * (1.f / 4096.f) - m * m;
            g_mean[bc] = m;
            g_rstd[bc] = rsqrtf(var + 1e-5f);
        }
    }
}

// ---------------- normalize + CLADE ----------------
__global__ void apply_kernel(const int* __restrict__ label, float* __restrict__ out)
{
    const int idx = blockIdx.x * 256 + threadIdx.x;
    const int b = idx >> 19;
    const int rem = idx & 524287;
    const int co = rem >> 10;
    const int hw4 = rem & 1023;

    float4 cv = ((const float4*)g_conv)[idx];
    int4 lb = ((const int4*)label)[b * 1024 + hw4];
    const float m = g_mean[b * CO_N + co];
    const float rs = g_rstd[b * CO_N + co];
    const float* cw = g_cwT + co * NCLS;
    const float* cb = g_cbT + co * NCLS;

    float4 o;
    o.x = (cv.x - m) * rs * cw[lb.x] + cb[lb.x];
    o.y = (cv.y - m) * rs * cw[lb.y] + cb[lb.y];
    o.z = (cv.z - m) * rs * cw[lb.z] + cb[lb.z];
    o.w = (cv.w - m) * rs * cw[lb.w] + cb[lb.w];
    ((float4*)out)[idx] = o;
}

// ---------------- launch ----------------
extern "C" void kernel_launch(void* const* d_in, const int* in_sizes, int n_in,
                              void* d_out, int out_size)
{
    const float* input       = (const float*)d_in[0];
    const float* style       = (const float*)d_in[1];
    const float* class_style = (const float*)d_in[2];
    const float* weight      = (const float*)d_in[3];
    const float* mod_w       = (const float*)d_in[4];
    const float* mod_b       = (const float*)d_in[5];
    const float* cw_w        = (const float*)d_in[6];
    const float* cw_b        = (const float*)d_in[7];
    const float* cb_w        = (const float*)d_in[8];
    const float* cb_b        = (const float*)d_in[9];
    const int*   label       = (const int*)d_in[10];
    float* out = (float*)d_out;

    cudaFuncSetAttribute(conv_mma_kernel,
                         cudaFuncAttributeMaxDynamicSharedMemorySize, SMEMB);

    eqlin_kernel<<<(BB * CI_N + 7) / 8, 256>>>(style, mod_w, mod_b, BB, CI_N, 1, CI_N, 0);
    eqlin_kernel<<<(NCLS * CO_N + 7) / 8, 256>>>(class_style, cw_w, cw_b, NCLS, CO_N, NCLS, 1, 1);
    eqlin_kernel<<<(NCLS * CO_N + 7) / 8, 256>>>(class_style, cb_w, cb_b, NCLS, CO_N, NCLS, 1, 2);
    wfrag_kernel<<<(9 * CO_N * CI_N + 255) / 256, 256>>>(weight);
    xscale_kernel<<<(BB * CI_N * HWN) / 4 / 256, 256>>>(input);

    conv_mma_kernel<<<1024, 256, SMEMB>>>();

    stats_kernel<<<BB * CO_N, 256>>>();
    apply_kernel<<<(BB * CO_N * HWN) / 4 / 256, 256>>>(label, out);
}

// round 4
// speedup vs baseline: 12.0794x; 1.8180x over previous
#include <cuda_runtime.h>
#include <cuda_fp16.h>
#include <cstdint>

// Problem constants
#define BB    8
#define CI_N  512
#define CO_N  512
#define HWN   4096
#define NCLS  35
#define SDIM  512

// conv smem geometry (units: uint32 = half2)
#define XPITCH 76
#define XCISTR (6 * XPITCH)          // 456 uint32 per ci2 slab
#define XBUFB  (8 * XCISTR * 4)      // 14592 B per X buffer (8 ci2 = 16 ci)
#define WBUFB  18432                 // 4 co16 tiles * 9 tap * 32 lanes * 16B
#define SMEMB  (2 * XBUFB + 2 * WBUFB)   // 66048 B

// ---------------- scratch (device globals) ----------------
__device__ float g_s[BB * CI_N];
__device__ float g_cwT[CO_N * NCLS];
__device__ float g_cbT[CO_N * NCLS];
__device__ __half g_wAh[(size_t)9 * CO_N * CI_N];        // fp16 A-fragment order
__device__ uint32_t g_xh[(size_t)BB * (CI_N / 2) * HWN]; // half2(ci even, ci odd)
__device__ float g_conv[(size_t)BB * CO_N * HWN];
__device__ float g_mean[BB * CO_N];
__device__ float g_rstd[BB * CO_N];

// ---------------- helpers ----------------
__device__ __forceinline__ uint32_t smem_u32(const void* p) {
    uint32_t a;
    asm("{ .reg .u64 t; cvta.to.shared.u64 t, %1; cvt.u32.u64 %0, t; }" : "=r"(a) : "l"(p));
    return a;
}
__device__ __forceinline__ void cp_async16(uint32_t dst, const void* src) {
    asm volatile("cp.async.cg.shared.global [%0], [%1], 16;" :: "r"(dst), "l"(src) : "memory");
}
#define CP_COMMIT() asm volatile("cp.async.commit_group;" ::: "memory")
#define CP_WAIT(n)  asm volatile("cp.async.wait_group %0;" :: "n"(n) : "memory")
#define STS_ZERO4(a) asm volatile("st.shared.v4.b32 [%0], {%1,%1,%1,%1};" :: "r"(a), "r"(0) : "memory")

__device__ __forceinline__ void mma16(float* c, uint4 a, uint32_t b0, uint32_t b1) {
    asm volatile(
        "mma.sync.aligned.m16n8k16.row.col.f32.f16.f16.f32 "
        "{%0,%1,%2,%3}, {%4,%5,%6,%7}, {%8,%9}, {%0,%1,%2,%3};"
        : "+f"(c[0]), "+f"(c[1]), "+f"(c[2]), "+f"(c[3])
        : "r"(a.x), "r"(a.y), "r"(a.z), "r"(a.w), "r"(b0), "r"(b1));
}
__device__ __forceinline__ uint32_t pack_h2(float a, float b) {
    __half2 h = __floats2half2_rn(a, b);
    return *(uint32_t*)&h;
}

// ---------------- EqualLinear ----------------
__global__ void eqlin_kernel(const float* __restrict__ X, const float* __restrict__ W,
                             const float* __restrict__ bias,
                             int M, int N, int sj, int si, int which)
{
    int wg = (blockIdx.x * blockDim.x + threadIdx.x) >> 5;
    int lane = threadIdx.x & 31;
    if (wg >= M * N) return;
    int i = wg / N, j = wg - i * N;
    const float4* x4 = (const float4*)(X + (size_t)i * SDIM);
    const float4* w4 = (const float4*)(W + (size_t)j * SDIM);
    float acc = 0.f;
#pragma unroll
    for (int q = 0; q < 4; q++) {
        float4 a = x4[lane + q * 32], b = w4[lane + q * 32];
        acc += a.x * b.x + a.y * b.y + a.z * b.z + a.w * b.w;
    }
#pragma unroll
    for (int o = 16; o > 0; o >>= 1) acc += __shfl_xor_sync(0xffffffffu, acc, o);
    if (lane == 0) {
        float v = acc * 0.04419417382415922f + bias[j];
        float* dst = (which == 0) ? g_s : (which == 1) ? g_cwT : g_cbT;
        dst[j * sj + i * si] = v;
    }
}

// ---------------- weights -> fp16 m16n8k16 A-fragment order ----------------
// g_wAh[(((co16_t*32 + c)*9 + tap)*32 + lane)*8 + j]
__global__ void wfrag_kernel(const float* __restrict__ w)
{
    int hidx = blockIdx.x * 256 + threadIdx.x;
    if (hidx >= 9 * CO_N * CI_N) return;
    int j = hidx & 7;
    int lane = (hidx >> 3) & 31;
    int tap = (hidx >> 8) % 9;
    int c = (hidx / 2304) & 31;
    int co16 = hidx / 73728;
    int g = lane >> 2, t = lane & 3;
    int co = co16 * 16 + g + ((j >> 1) & 1) * 8;
    int ci = c * 16 + 2 * t + (j & 1) + ((j >> 2) & 1) * 8;
    float v = w[((size_t)co * CI_N + ci) * 9 + tap];
    g_wAh[hidx] = __float2half_rn(v);
}

// ---------------- x * s -> half2(ci even, ci odd) per pixel ----------------
__global__ void xscale_kernel(const float* __restrict__ x)
{
    int idx = blockIdx.x * 256 + threadIdx.x;  // [b][ci2][hw4]
    int b = idx >> 18;
    int ci2 = (idx >> 10) & 255;
    int hw4 = idx & 1023;
    float s0 = g_s[b * CI_N + 2 * ci2];
    float s1 = g_s[b * CI_N + 2 * ci2 + 1];
    const float4* xe = (const float4*)(x + ((size_t)b * CI_N + 2 * ci2) * HWN);
    const float4* xo = (const float4*)(x + ((size_t)b * CI_N + 2 * ci2 + 1) * HWN);
    float4 e = xe[hw4], o = xo[hw4];
    uint4 r;
    r.x = pack_h2(e.x * s0, o.x * s1);
    r.y = pack_h2(e.y * s0, o.y * s1);
    r.z = pack_h2(e.z * s0, o.z * s1);
    r.w = pack_h2(e.w * s0, o.w * s1);
    ((uint4*)g_xh)[((size_t)b * 256 + ci2) * 1024 + hw4] = r;
}

// ---------------- conv: implicit GEMM via mma.sync fp16 ----------------
__device__ __forceinline__ void stage(char* sm, int buf, int c,
                                      const uint32_t* xsrc, const __half* wsrc,
                                      int r0, int tid)
{
    // X: 8 ci2 x 6 rows x 64 px (uint32) -> 768 x 16B
    uint32_t xb = smem_u32(sm) + buf * XBUFB;
#pragma unroll
    for (int k = 0; k < 3; k++) {
        int idx = tid + k * 256;
        int ci2 = idx / 96;
        int rem = idx - ci2 * 96;
        int srow = rem >> 4;
        int q = rem & 15;
        uint32_t dst = xb + (uint32_t)ci2 * (XCISTR * 4) + srow * (XPITCH * 4) + 16 + q * 16;
        int gr = r0 - 1 + srow;
        if ((unsigned)gr < 64u)
            cp_async16(dst, xsrc + ((size_t)(c * 8 + ci2)) * HWN + gr * 64 + q * 4);
        else
            STS_ZERO4(dst);
    }
    // W: 4 co16 tiles x 2304 halves -> 1152 x 16B
    uint32_t wb = smem_u32(sm) + 2 * XBUFB + buf * WBUFB;
#pragma unroll
    for (int k = 0; k < 4; k++) {
        int idx = tid + k * 256;
        int cs = idx / 288;
        int r = idx - cs * 288;
        cp_async16(wb + cs * 4608 + r * 16,
                   wsrc + ((size_t)cs * 32 + c) * 2304 + r * 8);
    }
    if (tid < 128) {
        int idx = 1024 + tid;
        int cs = idx / 288;
        int r = idx - cs * 288;
        cp_async16(wb + cs * 4608 + r * 16,
                   wsrc + ((size_t)cs * 32 + c) * 2304 + r * 8);
    }
}

__global__ void __launch_bounds__(256, 2) conv_mma_kernel()
{
    extern __shared__ char sm[];
    const int tid = threadIdx.x;
    const int bx = blockIdx.x;
    const int rb = bx & 15, cb = (bx >> 4) & 7, b = bx >> 7;
    const int r0 = rb * 4, co0 = cb * 64;
    const int wid = tid >> 5, lane = tid & 31;
    const int wco = wid & 1, wrow = wid >> 1;
    const int g = lane >> 2, t = lane & 3;

    const uint32_t* xsrc = g_xh + (size_t)b * 256 * HWN;
    const __half* wsrc = g_wAh + (size_t)(cb * 4) * 32 * 2304;

    // zero halo columns (uint32 slots 3 and 68 of each row), both buffers
    if (tid < 96) {
        int bufz = tid / 48;
        int rr = tid - bufz * 48;
        int ci2 = rr / 6, srow = rr - ci2 * 6;
        uint32_t* rbase = (uint32_t*)(sm + bufz * XBUFB) + ci2 * XCISTR + srow * XPITCH;
        rbase[3] = 0u;
        rbase[68] = 0u;
    }

    float C[2][8][4];
#pragma unroll
    for (int m = 0; m < 2; m++)
#pragma unroll
        for (int tn = 0; tn < 8; tn++)
#pragma unroll
            for (int j = 0; j < 4; j++) C[m][tn][j] = 0.f;

    stage(sm, 0, 0, xsrc, wsrc, r0, tid); CP_COMMIT();
    stage(sm, 1, 1, xsrc, wsrc, r0, tid); CP_COMMIT();

    for (int c = 0; c < 32; c++) {
        const int buf = c & 1;
        CP_WAIT(1);
        __syncthreads();
        const uint4* wbb = (const uint4*)(sm + 2 * XBUFB + buf * WBUFB);
        const uint32_t* xbb = (const uint32_t*)(sm + buf * XBUFB);
#pragma unroll
        for (int ky = 0; ky < 3; ky++) {
#pragma unroll
            for (int kx = 0; kx < 3; kx++) {
                const int tap = ky * 3 + kx;
                uint4 A0 = wbb[((2 * wco + 0) * 9 + tap) * 32 + lane];
                uint4 A1 = wbb[((2 * wco + 1) * 9 + tap) * 32 + lane];
                const uint32_t* xr = xbb + t * XCISTR + (wrow + ky) * XPITCH + 3 + g + kx;
#pragma unroll
                for (int tn = 0; tn < 8; tn++) {
                    uint32_t b0 = xr[tn * 8];
                    uint32_t b1 = xr[tn * 8 + 4 * XCISTR];
                    mma16(C[0][tn], A0, b0, b1);
                    mma16(C[1][tn], A1, b0, b1);
                }
            }
        }
        __syncthreads();
        if (c + 2 < 32) stage(sm, buf, c + 2, xsrc, wsrc, r0, tid);
        CP_COMMIT();
    }

    // epilogue
    const int row = r0 + wrow;
#pragma unroll
    for (int m = 0; m < 2; m++) {
        int co = co0 + wco * 32 + m * 16 + g;
        float* base0 = g_conv + ((size_t)(b * CO_N + co)) * HWN + row * 64;
#pragma unroll
        for (int tn = 0; tn < 8; tn++) {
            int col = tn * 8 + 2 * t;
            *(float2*)(base0 + col) = make_float2(C[m][tn][0], C[m][tn][1]);
            *(float2*)(base0 + (size_t)8 * HWN + col) = make_float2(C[m][tn][2], C[m][tn][3]);
        }
    }
}

// ---------------- Instance-norm statistics ----------------
__global__ void stats_kernel()
{
    const int bc = blockIdx.x;
    const float4* p = (const float4*)(g_conv + (size_t)bc * HWN);
    const int t = threadIdx.x;
    float s1 = 0.f, s2 = 0.f;
#pragma unroll
    for (int q = 0; q < 4; q++) {
        float4 v = p[t + q * 256];
        s1 += v.x + v.y + v.z + v.w;
        s2 += v.x * v.x + v.y * v.y + v.z * v.z + v.w * v.w;
    }
#pragma unroll
    for (int o = 16; o > 0; o >>= 1) {
        s1 += __shfl_xor_sync(0xffffffffu, s1, o);
        s2 += __shfl_xor_sync(0xffffffffu, s2, o);
    }
    __shared__ float r1[8], r2[8];
    if ((t & 31) == 0) { r1[t >> 5] = s1; r2[t >> 5] = s2; }
    __syncthreads();
    if (t < 8) {
        s1 = r1[t]; s2 = r2[t];
#pragma unroll
        for (int o = 4; o > 0; o >>= 1) {
            s1 += __shfl_xor_sync(0xffu, s1, o);
            s2 += __shfl_xor_sync(0xffu, s2, o);
        }
        if (t == 0) {
            float m = s1 * (1.f / 4096.f);
            float var = s2 * (1.f / 4096.f) - m * m;
            g_mean[bc] = m;
            g_rstd[bc] = rsqrtf(var + 1e-5f);
        }
    }
}

// ---------------- normalize + CLADE ----------------
__global__ void apply_kernel(const int* __restrict__ label, float* __restrict__ out)
{
    const int idx = blockIdx.x * 256 + threadIdx.x;
    const int b = idx >> 19;
    const int rem = idx & 524287;
    const int co = rem >> 10;
    const int hw4 = rem & 1023;

    float4 cv = ((const float4*)g_conv)[idx];
    int4 lb = ((const int4*)label)[b * 1024 + hw4];
    const float m = g_mean[b * CO_N + co];
    const float rs = g_rstd[b * CO_N + co];
    const float* cw = g_cwT + co * NCLS;
    const float* cb = g_cbT + co * NCLS;

    float4 o;
    o.x = (cv.x - m) * rs * cw[lb.x] + cb[lb.x];
    o.y = (cv.y - m) * rs * cw[lb.y] + cb[lb.y];
    o.z = (cv.z - m) * rs * cw[lb.z] + cb[lb.z];
    o.w = (cv.w - m) * rs * cw[lb.w] + cb[lb.w];
    ((float4*)out)[idx] = o;
}

// ---------------- launch ----------------
extern "C" void kernel_launch(void* const* d_in, const int* in_sizes, int n_in,
                              void* d_out, int out_size)
{
    const float* input       = (const float*)d_in[0];
    const float* style       = (const float*)d_in[1];
    const float* class_style = (const float*)d_in[2];
    const float* weight      = (const float*)d_in[3];
    const float* mod_w       = (const float*)d_in[4];
    const float* mod_b       = (const float*)d_in[5];
    const float* cw_w        = (const float*)d_in[6];
    const float* cw_b        = (const float*)d_in[7];
    const float* cb_w        = (const float*)d_in[8];
    const float* cb_b        = (const float*)d_in[9];
    const int*   label       = (const int*)d_in[10];
    float* out = (float*)d_out;

    cudaFuncSetAttribute(conv_mma_kernel,
                         cudaFuncAttributeMaxDynamicSharedMemorySize, SMEMB);

    eqlin_kernel<<<(BB * CI_N + 7) / 8, 256>>>(style, mod_w, mod_b, BB, CI_N, 1, CI_N, 0);
    eqlin_kernel<<<(NCLS * CO_N + 7) / 8, 256>>>(class_style, cw_w, cw_b, NCLS, CO_N, NCLS, 1, 1);
    eqlin_kernel<<<(NCLS * CO_N + 7) / 8, 256>>>(class_style, cb_w, cb_b, NCLS, CO_N, NCLS, 1, 2);
    wfrag_kernel<<<(9 * CO_N * CI_N + 255) / 256, 256>>>(weight);
    xscale_kernel<<<(BB * (CI_N / 2) * HWN) / 4 / 256, 256>>>(input);

    conv_mma_kernel<<<1024, 256, SMEMB>>>();

    stats_kernel<<<BB * CO_N, 256>>>();
    apply_kernel<<<(BB * CO_N * HWN) / 4 / 256, 256>>>(label, out);
}

// round 5
// speedup vs baseline: 12.0842x; 1.0004x over previous
#include <cuda_runtime.h>
#include <cuda_fp16.h>
#include <cstdint>

// Problem constants
#define BB    8
#define CI_N  512
#define CO_N  512
#define HWN   4096
#define NCLS  35
#define SDIM  512

// conv smem geometry (units: uint32 = half2)
#define XPITCH 76
#define XCISTR (6 * XPITCH)          // 456 uint32 per ci2 slab
#define XBUFB  (8 * XCISTR * 4)      // 14592 B per X buffer (8 ci2 = 16 ci)
#define WBUFB  18432                 // 4 co16 tiles * 9 tap * 32 lanes * 16B
#define SMEMB  (2 * XBUFB + 2 * WBUFB)   // 66048 B

// ---------------- scratch (device globals) ----------------
__device__ float g_s[BB * CI_N];
__device__ float g_cwT[CO_N * NCLS];
__device__ float g_cbT[CO_N * NCLS];
__device__ __half g_wAh[(size_t)9 * CO_N * CI_N];        // fp16 A-fragment order
__device__ uint32_t g_xh[(size_t)BB * (CI_N / 2) * HWN]; // half2(ci even, ci odd)
__device__ float g_conv[(size_t)BB * CO_N * HWN];
__device__ float g_mean[BB * CO_N];
__device__ float g_rstd[BB * CO_N];

// ---------------- helpers ----------------
__device__ __forceinline__ uint32_t smem_u32(const void* p) {
    uint32_t a;
    asm("{ .reg .u64 t; cvta.to.shared.u64 t, %1; cvt.u32.u64 %0, t; }" : "=r"(a) : "l"(p));
    return a;
}
__device__ __forceinline__ void cp_async16(uint32_t dst, const void* src) {
    asm volatile("cp.async.cg.shared.global [%0], [%1], 16;" :: "r"(dst), "l"(src) : "memory");
}
#define CP_COMMIT() asm volatile("cp.async.commit_group;" ::: "memory")
#define CP_WAIT(n)  asm volatile("cp.async.wait_group %0;" :: "n"(n) : "memory")
#define STS_ZERO4(a) asm volatile("st.shared.v4.b32 [%0], {%1,%1,%1,%1};" :: "r"(a), "r"(0) : "memory")

__device__ __forceinline__ void mma16(float* c, uint4 a, uint32_t b0, uint32_t b1) {
    asm volatile(
        "mma.sync.aligned.m16n8k16.row.col.f32.f16.f16.f32 "
        "{%0,%1,%2,%3}, {%4,%5,%6,%7}, {%8,%9}, {%0,%1,%2,%3};"
        : "+f"(c[0]), "+f"(c[1]), "+f"(c[2]), "+f"(c[3])
        : "r"(a.x), "r"(a.y), "r"(a.z), "r"(a.w), "r"(b0), "r"(b1));
}
__device__ __forceinline__ uint32_t pack_h2(float a, float b) {
    __half2 h = __floats2half2_rn(a, b);
    return *(uint32_t*)&h;
}

// ---------------- EqualLinear ----------------
__global__ void eqlin_kernel(const float* __restrict__ X, const float* __restrict__ W,
                             const float* __restrict__ bias,
                             int M, int N, int sj, int si, int which)
{
    int wg = (blockIdx.x * blockDim.x + threadIdx.x) >> 5;
    int lane = threadIdx.x & 31;
    if (wg >= M * N) return;
    int i = wg / N, j = wg - i * N;
    const float4* x4 = (const float4*)(X + (size_t)i * SDIM);
    const float4* w4 = (const float4*)(W + (size_t)j * SDIM);
    float acc = 0.f;
#pragma unroll
    for (int q = 0; q < 4; q++) {
        float4 a = x4[lane + q * 32], b = w4[lane + q * 32];
        acc += a.x * b.x + a.y * b.y + a.z * b.z + a.w * b.w;
    }
#pragma unroll
    for (int o = 16; o > 0; o >>= 1) acc += __shfl_xor_sync(0xffffffffu, acc, o);
    if (lane == 0) {
        float v = acc * 0.04419417382415922f + bias[j];
        float* dst = (which == 0) ? g_s : (which == 1) ? g_cwT : g_cbT;
        dst[j * sj + i * si] = v;
    }
}

// ---------------- weights -> fp16 m16n8k16 A-fragment order ----------------
// g_wAh[(((co16_t*32 + c)*9 + tap)*32 + lane)*8 + j]
__global__ void wfrag_kernel(const float* __restrict__ w)
{
    int hidx = blockIdx.x * 256 + threadIdx.x;
    if (hidx >= 9 * CO_N * CI_N) return;
    int j = hidx & 7;
    int lane = (hidx >> 3) & 31;
    int tap = (hidx >> 8) % 9;
    int c = (hidx / 2304) & 31;
    int co16 = hidx / 73728;
    int g = lane >> 2, t = lane & 3;
    int co = co16 * 16 + g + ((j >> 1) & 1) * 8;
    int ci = c * 16 + 2 * t + (j & 1) + ((j >> 2) & 1) * 8;
    float v = w[((size_t)co * CI_N + ci) * 9 + tap];
    g_wAh[hidx] = __float2half_rn(v);
}

// ---------------- x * s -> half2(ci even, ci odd) per pixel ----------------
__global__ void xscale_kernel(const float* __restrict__ x)
{
    int idx = blockIdx.x * 256 + threadIdx.x;  // [b][ci2][hw4]
    int b = idx >> 18;
    int ci2 = (idx >> 10) & 255;
    int hw4 = idx & 1023;
    float s0 = g_s[b * CI_N + 2 * ci2];
    float s1 = g_s[b * CI_N + 2 * ci2 + 1];
    const float4* xe = (const float4*)(x + ((size_t)b * CI_N + 2 * ci2) * HWN);
    const float4* xo = (const float4*)(x + ((size_t)b * CI_N + 2 * ci2 + 1) * HWN);
    float4 e = xe[hw4], o = xo[hw4];
    uint4 r;
    r.x = pack_h2(e.x * s0, o.x * s1);
    r.y = pack_h2(e.y * s0, o.y * s1);
    r.z = pack_h2(e.z * s0, o.z * s1);
    r.w = pack_h2(e.w * s0, o.w * s1);
    ((uint4*)g_xh)[((size_t)b * 256 + ci2) * 1024 + hw4] = r;
}

// ---------------- conv: implicit GEMM via mma.sync fp16 ----------------
__device__ __forceinline__ void stage(char* sm, int buf, int c,
                                      const uint32_t* xsrc, const __half* wsrc,
                                      int r0, int tid)
{
    // X: 8 ci2 x 6 rows x 64 px (uint32) -> 768 x 16B
    uint32_t xb = smem_u32(sm) + buf * XBUFB;
#pragma unroll
    for (int k = 0; k < 3; k++) {
        int idx = tid + k * 256;
        int ci2 = idx / 96;
        int rem = idx - ci2 * 96;
        int srow = rem >> 4;
        int q = rem & 15;
        uint32_t dst = xb + (uint32_t)ci2 * (XCISTR * 4) + srow * (XPITCH * 4) + 16 + q * 16;
        int gr = r0 - 1 + srow;
        if ((unsigned)gr < 64u)
            cp_async16(dst, xsrc + ((size_t)(c * 8 + ci2)) * HWN + gr * 64 + q * 4);
        else
            STS_ZERO4(dst);
    }
    // W: 4 co16 tiles x 2304 halves -> 1152 x 16B
    uint32_t wb = smem_u32(sm) + 2 * XBUFB + buf * WBUFB;
#pragma unroll
    for (int k = 0; k < 4; k++) {
        int idx = tid + k * 256;
        int cs = idx / 288;
        int r = idx - cs * 288;
        cp_async16(wb + cs * 4608 + r * 16,
                   wsrc + ((size_t)cs * 32 + c) * 2304 + r * 8);
    }
    if (tid < 128) {
        int idx = 1024 + tid;
        int cs = idx / 288;
        int r = idx - cs * 288;
        cp_async16(wb + cs * 4608 + r * 16,
                   wsrc + ((size_t)cs * 32 + c) * 2304 + r * 8);
    }
}

__global__ void __launch_bounds__(256, 2) conv_mma_kernel()
{
    extern __shared__ char sm[];
    const int tid = threadIdx.x;
    const int bx = blockIdx.x;
    const int rb = bx & 15, cb = (bx >> 4) & 7, b = bx >> 7;
    const int r0 = rb * 4, co0 = cb * 64;
    const int wid = tid >> 5, lane = tid & 31;
    const int wco = wid & 1, wrow = wid >> 1;
    const int g = lane >> 2, t = lane & 3;

    const uint32_t* xsrc = g_xh + (size_t)b * 256 * HWN;
    const __half* wsrc = g_wAh + (size_t)(cb * 4) * 32 * 2304;

    // zero halo columns (uint32 slots 3 and 68 of each row), both buffers
    if (tid < 96) {
        int bufz = tid / 48;
        int rr = tid - bufz * 48;
        int ci2 = rr / 6, srow = rr - ci2 * 6;
        uint32_t* rbase = (uint32_t*)(sm + bufz * XBUFB) + ci2 * XCISTR + srow * XPITCH;
        rbase[3] = 0u;
        rbase[68] = 0u;
    }

    float C[2][8][4];
#pragma unroll
    for (int m = 0; m < 2; m++)
#pragma unroll
        for (int tn = 0; tn < 8; tn++)
#pragma unroll
            for (int j = 0; j < 4; j++) C[m][tn][j] = 0.f;

    stage(sm, 0, 0, xsrc, wsrc, r0, tid); CP_COMMIT();
    stage(sm, 1, 1, xsrc, wsrc, r0, tid); CP_COMMIT();

    for (int c = 0; c < 32; c++) {
        const int buf = c & 1;
        CP_WAIT(1);
        __syncthreads();
        const uint4* wbb = (const uint4*)(sm + 2 * XBUFB + buf * WBUFB);
        const uint32_t* xbb = (const uint32_t*)(sm + buf * XBUFB);
#pragma unroll
        for (int ky = 0; ky < 3; ky++) {
#pragma unroll
            for (int kx = 0; kx < 3; kx++) {
                const int tap = ky * 3 + kx;
                uint4 A0 = wbb[((2 * wco + 0) * 9 + tap) * 32 + lane];
                uint4 A1 = wbb[((2 * wco + 1) * 9 + tap) * 32 + lane];
                const uint32_t* xr = xbb + t * XCISTR + (wrow + ky) * XPITCH + 3 + g + kx;
#pragma unroll
                for (int tn = 0; tn < 8; tn++) {
                    uint32_t b0 = xr[tn * 8];
                    uint32_t b1 = xr[tn * 8 + 4 * XCISTR];
                    mma16(C[0][tn], A0, b0, b1);
                    mma16(C[1][tn], A1, b0, b1);
                }
            }
        }
        __syncthreads();
        if (c + 2 < 32) stage(sm, buf, c + 2, xsrc, wsrc, r0, tid);
        CP_COMMIT();
    }

    // epilogue
    const int row = r0 + wrow;
#pragma unroll
    for (int m = 0; m < 2; m++) {
        int co = co0 + wco * 32 + m * 16 + g;
        float* base0 = g_conv + ((size_t)(b * CO_N + co)) * HWN + row * 64;
#pragma unroll
        for (int tn = 0; tn < 8; tn++) {
            int col = tn * 8 + 2 * t;
            *(float2*)(base0 + col) = make_float2(C[m][tn][0], C[m][tn][1]);
            *(float2*)(base0 + (size_t)8 * HWN + col) = make_float2(C[m][tn][2], C[m][tn][3]);
        }
    }
}

// ---------------- Instance-norm statistics ----------------
__global__ void stats_kernel()
{
    const int bc = blockIdx.x;
    const float4* p = (const float4*)(g_conv + (size_t)bc * HWN);
    const int t = threadIdx.x;
    float s1 = 0.f, s2 = 0.f;
#pragma unroll
    for (int q = 0; q < 4; q++) {
        float4 v = p[t + q * 256];
        s1 += v.x + v.y + v.z + v.w;
        s2 += v.x * v.x + v.y * v.y + v.z * v.z + v.w * v.w;
    }
#pragma unroll
    for (int o = 16; o > 0; o >>= 1) {
        s1 += __shfl_xor_sync(0xffffffffu, s1, o);
        s2 += __shfl_xor_sync(0xffffffffu, s2, o);
    }
    __shared__ float r1[8], r2[8];
    if ((t & 31) == 0) { r1[t >> 5] = s1; r2[t >> 5] = s2; }
    __syncthreads();
    if (t < 8) {
        s1 = r1[t]; s2 = r2[t];
#pragma unroll
        for (int o = 4; o > 0; o >>= 1) {
            s1 += __shfl_xor_sync(0xffu, s1, o);
            s2 += __shfl_xor_sync(0xffu, s2, o);
        }
        if (t == 0) {
            float m = s1 * (1.f / 4096.f);
            float var = s2 * (1.f / 4096.f) - m * m;
            g_mean[bc] = m;
            g_rstd[bc] = rsqrtf(var + 1e-5f);
        }
    }
}

// ---------------- normalize + CLADE ----------------
__global__ void apply_kernel(const int* __restrict__ label, float* __restrict__ out)
{
    const int idx = blockIdx.x * 256 + threadIdx.x;
    const int b = idx >> 19;
    const int rem = idx & 524287;
    const int co = rem >> 10;
    const int hw4 = rem & 1023;

    float4 cv = ((const float4*)g_conv)[idx];
    int4 lb = ((const int4*)label)[b * 1024 + hw4];
    const float m = g_mean[b * CO_N + co];
    const float rs = g_rstd[b * CO_N + co];
    const float* cw = g_cwT + co * NCLS;
    const float* cb = g_cbT + co * NCLS;

    float4 o;
    o.x = (cv.x - m) * rs * cw[lb.x] + cb[lb.x];
    o.y = (cv.y - m) * rs * cw[lb.y] + cb[lb.y];
    o.z = (cv.z - m) * rs * cw[lb.z] + cb[lb.z];
    o.w = (cv.w - m) * rs * cw[lb.w] + cb[lb.w];
    ((float4*)out)[idx] = o;
}

// ---------------- launch ----------------
extern "C" void kernel_launch(void* const* d_in, const int* in_sizes, int n_in,
                              void* d_out, int out_size)
{
    const float* input       = (const float*)d_in[0];
    const float* style       = (const float*)d_in[1];
    const float* class_style = (const float*)d_in[2];
    const float* weight      = (const float*)d_in[3];
    const float* mod_w       = (const float*)d_in[4];
    const float* mod_b       = (const float*)d_in[5];
    const float* cw_w        = (const float*)d_in[6];
    const float* cw_b        = (const float*)d_in[7];
    const float* cb_w        = (const float*)d_in[8];
    const float* cb_b        = (const float*)d_in[9];
    const int*   label       = (const int*)d_in[10];
    float* out = (float*)d_out;

    cudaFuncSetAttribute(conv_mma_kernel,
                         cudaFuncAttributeMaxDynamicSharedMemorySize, SMEMB);

    eqlin_kernel<<<(BB * CI_N + 7) / 8, 256>>>(style, mod_w, mod_b, BB, CI_N, 1, CI_N, 0);
    eqlin_kernel<<<(NCLS * CO_N + 7) / 8, 256>>>(class_style, cw_w, cw_b, NCLS, CO_N, NCLS, 1, 1);
    eqlin_kernel<<<(NCLS * CO_N + 7) / 8, 256>>>(class_style, cb_w, cb_b, NCLS, CO_N, NCLS, 1, 2);
    wfrag_kernel<<<(9 * CO_N * CI_N + 255) / 256, 256>>>(weight);
    xscale_kernel<<<(BB * (CI_N / 2) * HWN) / 4 / 256, 256>>>(input);

    conv_mma_kernel<<<1024, 256, SMEMB>>>();

    stats_kernel<<<BB * CO_N, 256>>>();
    apply_kernel<<<(BB * CO_N * HWN) / 4 / 256, 256>>>(label, out);
}

// round 6
// speedup vs baseline: 12.6972x; 1.0507x over previous
#include <cuda_runtime.h>
#include <cuda_fp16.h>
#include <cstdint>

// Problem constants
#define BB    8
#define CI_N  512
#define CO_N  512
#define HWN   4096
#define NCLS  35
#define SDIM  512
#define NT    8192              // total output tiles: 8 b * 32*32

// ---------------- scratch (device globals) ----------------
__device__ float g_s[BB * CI_N];
__device__ float g_cwT[CO_N * NCLS];
__device__ float g_cbT[CO_N * NCLS];
__device__ __half g_U[(size_t)16 * CO_N * CI_N];          // fragment-ordered Winograd weights
__device__ uint32_t g_V[(size_t)16 * (CI_N / 2) * NT];    // half2(ci even, ci odd)
__device__ float g_M[(size_t)16 * CO_N * NT];             // GEMM results (fp32, 268MB)
__device__ float g_conv[(size_t)BB * CO_N * HWN];
__device__ float g_mean[BB * CO_N];
__device__ float g_rstd[BB * CO_N];

// ---------------- helpers ----------------
__device__ __forceinline__ uint32_t smem_u32(const void* p) {
    uint32_t a;
    asm("{ .reg .u64 t; cvta.to.shared.u64 t, %1; cvt.u32.u64 %0, t; }" : "=r"(a) : "l"(p));
    return a;
}
__device__ __forceinline__ void cp_async16(uint32_t dst, const void* src) {
    asm volatile("cp.async.cg.shared.global [%0], [%1], 16;" :: "r"(dst), "l"(src) : "memory");
}
#define CP_COMMIT() asm volatile("cp.async.commit_group;" ::: "memory")
#define CP_WAIT(n)  asm volatile("cp.async.wait_group %0;" :: "n"(n) : "memory")

__device__ __forceinline__ void mma16(float* c, uint4 a, uint32_t b0, uint32_t b1) {
    asm volatile(
        "mma.sync.aligned.m16n8k16.row.col.f32.f16.f16.f32 "
        "{%0,%1,%2,%3}, {%4,%5,%6,%7}, {%8,%9}, {%0,%1,%2,%3};"
        : "+f"(c[0]), "+f"(c[1]), "+f"(c[2]), "+f"(c[3])
        : "r"(a.x), "r"(a.y), "r"(a.z), "r"(a.w), "r"(b0), "r"(b1));
}
__device__ __forceinline__ uint32_t pack_h2(float a, float b) {
    __half2 h = __floats2half2_rn(a, b);
    return *(uint32_t*)&h;
}

// ---------------- EqualLinear ----------------
__global__ void eqlin_kernel(const float* __restrict__ X, const float* __restrict__ W,
                             const float* __restrict__ bias,
                             int M, int N, int sj, int si, int which)
{
    int wg = (blockIdx.x * blockDim.x + threadIdx.x) >> 5;
    int lane = threadIdx.x & 31;
    if (wg >= M * N) return;
    int i = wg / N, j = wg - i * N;
    const float4* x4 = (const float4*)(X + (size_t)i * SDIM);
    const float4* w4 = (const float4*)(W + (size_t)j * SDIM);
    float acc = 0.f;
#pragma unroll
    for (int q = 0; q < 4; q++) {
        float4 a = x4[lane + q * 32], b = w4[lane + q * 32];
        acc += a.x * b.x + a.y * b.y + a.z * b.z + a.w * b.w;
    }
#pragma unroll
    for (int o = 16; o > 0; o >>= 1) acc += __shfl_xor_sync(0xffffffffu, acc, o);
    if (lane == 0) {
        float v = acc * 0.04419417382415922f + bias[j];
        float* dst = (which == 0) ? g_s : (which == 1) ? g_cwT : g_cbT;
        dst[j * sj + i * si] = v;
    }
}

// ---------------- U-prep: U = G g G^T per (co,ci), fragment-ordered fp16 ----------------
// g_U[((((e*8 + cob)*32 + c)*4 + mt)*32 + lane)*8 + j]
__global__ void uprep_kernel(const float* __restrict__ w)
{
    int idx = blockIdx.x * 256 + threadIdx.x;      // co*512 + ci
    if (idx >= CO_N * CI_N) return;
    int co = idx >> 9, ci = idx & 511;
    const float* gp = w + (size_t)idx * 9;
    float g0[3] = {gp[0], gp[1], gp[2]};
    float g1[3] = {gp[3], gp[4], gp[5]};
    float g2[3] = {gp[6], gp[7], gp[8]};
    float T[4][3], U[4][4];
#pragma unroll
    for (int c = 0; c < 3; c++) {
        T[0][c] = g0[c];
        T[1][c] = 0.5f * (g0[c] + g1[c] + g2[c]);
        T[2][c] = 0.5f * (g0[c] - g1[c] + g2[c]);
        T[3][c] = g2[c];
    }
#pragma unroll
    for (int r = 0; r < 4; r++) {
        U[r][0] = T[r][0];
        U[r][1] = 0.5f * (T[r][0] + T[r][1] + T[r][2]);
        U[r][2] = 0.5f * (T[r][0] - T[r][1] + T[r][2]);
        U[r][3] = T[r][2];
    }
    // fragment coordinates
    int cob = co >> 6;
    int c16 = ci >> 4;
    int mt = (co >> 4) & 3;
    int gg = co & 7;
    int j1 = (co >> 3) & 1;
    int t = (ci >> 1) & 3;
    int j0 = ci & 1;
    int j2 = (ci >> 3) & 1;
    int lane = (gg << 2) | t;
    int j = j0 | (j1 << 1) | (j2 << 2);
#pragma unroll
    for (int e = 0; e < 16; e++) {
        size_t addr = ((((size_t)e * 8 + cob) * 32 + c16) * 4 + mt) * 256 + lane * 8 + j;
        g_U[addr] = __float2half_rn(U[e >> 2][e & 3]);
    }
}

// ---------------- V-prep: V = B^T d B per 4x4 patch, style-scaled, half2 packed ----------------
__global__ void __launch_bounds__(256) vprep_kernel(const float* __restrict__ x)
{
    __shared__ float xs[2 * 66 * 66];
    const int tid = threadIdx.x;
    const int b = blockIdx.x >> 8;
    const int ci2 = blockIdx.x & 255;

    // zero padded buffer
    for (int i = tid; i < 2 * 66 * 66; i += 256) xs[i] = 0.f;
    __syncthreads();

    const float s0 = g_s[b * CI_N + 2 * ci2];
    const float s1 = g_s[b * CI_N + 2 * ci2 + 1];
    const float* x0 = x + ((size_t)b * CI_N + 2 * ci2) * HWN;
    const float* x1 = x0 + HWN;
    for (int i = tid; i < HWN; i += 256) {
        int r = i >> 6, c = i & 63;
        xs[(r + 1) * 66 + (c + 1)] = x0[i] * s0;
        xs[66 * 66 + (r + 1) * 66 + (c + 1)] = x1[i] * s1;
    }
    __syncthreads();

#pragma unroll 1
    for (int rep = 0; rep < 4; rep++) {
        int tpos = tid + rep * 256;
        int ty = tpos >> 5, tx = tpos & 31;
        float V2[2][4][4];
#pragma unroll
        for (int cin = 0; cin < 2; cin++) {
            const float* base = xs + cin * (66 * 66) + (2 * ty) * 66 + 2 * tx;
            float p[4][4];
#pragma unroll
            for (int r = 0; r < 4; r++)
#pragma unroll
                for (int c = 0; c < 4; c++) p[r][c] = base[r * 66 + c];
            float t1[4][4];
#pragma unroll
            for (int c = 0; c < 4; c++) {
                t1[0][c] = p[0][c] - p[2][c];
                t1[1][c] = p[1][c] + p[2][c];
                t1[2][c] = p[2][c] - p[1][c];
                t1[3][c] = p[1][c] - p[3][c];
            }
#pragma unroll
            for (int r = 0; r < 4; r++) {
                V2[cin][r][0] = t1[r][0] - t1[r][2];
                V2[cin][r][1] = t1[r][1] + t1[r][2];
                V2[cin][r][2] = t1[r][2] - t1[r][1];
                V2[cin][r][3] = t1[r][1] - t1[r][3];
            }
        }
        size_t n = (size_t)b * 1024 + tpos;
#pragma unroll
        for (int e = 0; e < 16; e++) {
            g_V[((size_t)e * 256 + ci2) * NT + n] =
                pack_h2(V2[0][e >> 2][e & 3], V2[1][e >> 2][e & 3]);
        }
    }
}

// ---------------- GEMM: M[e] = U[e] @ V[e]  (64co x 256n CTA tile) ----------------
#define BPITCH 264   // uint32 row pitch (264 % 32 == 8 -> conflict-free frag reads)

__device__ __forceinline__ void gstage(uint32_t ab, uint32_t bb, int e, int cob,
                                       int nb, int c, int tid)
{
    const __half* asrc = g_U + (((size_t)e * 8 + cob) * 32 + c) * 1024;
    if (tid < 128) cp_async16(ab + tid * 16, asrc + tid * 8);
    const uint32_t* bsrc = g_V + ((size_t)e * 256 + c * 8) * NT + nb * 256;
#pragma unroll
    for (int k = 0; k < 2; k++) {
        int idx = tid + k * 256;
        int r = idx >> 6, q = idx & 63;
        cp_async16(bb + (r * BPITCH + q * 4) * 4, bsrc + (size_t)r * NT + q * 4);
    }
}

__global__ void __launch_bounds__(256, 2) wgemm_kernel()
{
    __shared__ __align__(16) char smA[2][2048];
    __shared__ __align__(16) char smB[2][2 * BPITCH * 8 * 2];  // 8448B each

    const int tid = threadIdx.x;
    const int bx = blockIdx.x;
    const int nb = bx & 31, cob = (bx >> 5) & 7, e = bx >> 8;
    const int wid = tid >> 5, lane = tid & 31;
    const int wco = wid & 1, wn = wid >> 1;
    const int g = lane >> 2, t = lane & 3;

    const uint32_t ab0 = smem_u32(smA[0]), ab1 = smem_u32(smA[1]);
    const uint32_t bb0 = smem_u32(smB[0]), bb1 = smem_u32(smB[1]);

    float C[2][8][4];
#pragma unroll
    for (int m = 0; m < 2; m++)
#pragma unroll
        for (int tn = 0; tn < 8; tn++)
#pragma unroll
            for (int j = 0; j < 4; j++) C[m][tn][j] = 0.f;

    gstage(ab0, bb0, e, cob, nb, 0, tid); CP_COMMIT();
    gstage(ab1, bb1, e, cob, nb, 1, tid); CP_COMMIT();

    for (int c = 0; c < 32; c++) {
        const int buf = c & 1;
        CP_WAIT(1);
        __syncthreads();
        const uint4* abuf = (const uint4*)(buf ? smA[1] : smA[0]);
        const uint32_t* bbuf = (const uint32_t*)(buf ? smB[1] : smB[0]);

        uint4 A0 = abuf[(2 * wco + 0) * 32 + lane];
        uint4 A1 = abuf[(2 * wco + 1) * 32 + lane];
        const uint32_t* br0 = bbuf + t * BPITCH + wn * 64 + g;
        const uint32_t* br1 = bbuf + (t + 4) * BPITCH + wn * 64 + g;
#pragma unroll
        for (int tn = 0; tn < 8; tn++) {
            uint32_t b0 = br0[tn * 8];
            uint32_t b1 = br1[tn * 8];
            mma16(C[0][tn], A0, b0, b1);
            mma16(C[1][tn], A1, b0, b1);
        }
        __syncthreads();
        if (c + 2 < 32)
            gstage(buf ? ab1 : ab0, buf ? bb1 : bb0, e, cob, nb, c + 2, tid);
        CP_COMMIT();
    }

    // epilogue: write M fp32
#pragma unroll
    for (int m = 0; m < 2; m++) {
        int co = cob * 64 + wco * 32 + m * 16 + g;
        float* base = g_M + ((size_t)e * 512 + co) * NT + nb * 256 + wn * 64;
#pragma unroll
        for (int tn = 0; tn < 8; tn++) {
            int col = tn * 8 + 2 * t;
            *(float2*)(base + col) = make_float2(C[m][tn][0], C[m][tn][1]);
            *(float2*)(base + 8 * NT + col) = make_float2(C[m][tn][2], C[m][tn][3]);
        }
    }
}

// ---------------- output transform: Y = A^T M A ----------------
__global__ void outtrans_kernel()
{
    int idx = blockIdx.x * 256 + threadIdx.x;       // co*8192 + n
    int co = idx >> 13;
    int n = idx & 8191;
    int b = n >> 10, tpos = n & 1023;
    int ty = tpos >> 5, tx = tpos & 31;

    float m[16];
#pragma unroll
    for (int e = 0; e < 16; e++)
        m[e] = g_M[((size_t)e * 512 + co) * NT + idx % NT + (size_t)(co) * 0 + n - n + ((size_t)e * 512 + co) * 0] ;
    // (simplified below — overwrite with correct reads)
#pragma unroll
    for (int e = 0; e < 16; e++)
        m[e] = g_M[((size_t)e * 512 + co) * NT + n];

    float t0[4], t1[4];
#pragma unroll
    for (int c = 0; c < 4; c++) {
        t0[c] = m[0 + c] + m[4 + c] + m[8 + c];
        t1[c] = m[4 + c] - m[8 + c] - m[12 + c];
    }
    float y00 = t0[0] + t0[1] + t0[2];
    float y01 = t0[1] - t0[2] - t0[3];
    float y10 = t1[0] + t1[1] + t1[2];
    float y11 = t1[1] - t1[2] - t1[3];

    float* dst = g_conv + ((size_t)b * CO_N + co) * HWN + (2 * ty) * 64 + 2 * tx;
    *(float2*)dst = make_float2(y00, y01);
    *(float2*)(dst + 64) = make_float2(y10, y11);
}

// ---------------- Instance-norm statistics ----------------
__global__ void stats_kernel()
{
    const int bc = blockIdx.x;
    const float4* p = (const float4*)(g_conv + (size_t)bc * HWN);
    const int t = threadIdx.x;
    float s1 = 0.f, s2 = 0.f;
#pragma unroll
    for (int q = 0; q < 4; q++) {
        float4 v = p[t + q * 256];
        s1 += v.x + v.y + v.z + v.w;
        s2 += v.x * v.x + v.y * v.y + v.z * v.z + v.w * v.w;
    }
#pragma unroll
    for (int o = 16; o > 0; o >>= 1) {
        s1 += __shfl_xor_sync(0xffffffffu, s1, o);
        s2 += __shfl_xor_sync(0xffffffffu, s2, o);
    }
    __shared__ float r1[8], r2[8];
    if ((t & 31) == 0) { r1[t >> 5] = s1; r2[t >> 5] = s2; }
    __syncthreads();
    if (t < 8) {
        s1 = r1[t]; s2 = r2[t];
#pragma unroll
        for (int o = 4; o > 0; o >>= 1) {
            s1 += __shfl_xor_sync(0xffu, s1, o);
            s2 += __shfl_xor_sync(0xffu, s2, o);
        }
        if (t == 0) {
            float m = s1 * (1.f / 4096.f);
            float var = s2 * (1.f / 4096.f) - m * m;
            g_mean[bc] = m;
            g_rstd[bc] = rsqrtf(var + 1e-5f);
        }
    }
}

// ---------------- normalize + CLADE ----------------
__global__ void apply_kernel(const int* __restrict__ label, float* __restrict__ out)
{
    const int idx = blockIdx.x * 256 + threadIdx.x;
    const int b = idx >> 19;
    const int rem = idx & 524287;
    const int co = rem >> 10;
    const int hw4 = rem & 1023;

    float4 cv = ((const float4*)g_conv)[idx];
    int4 lb = ((const int4*)label)[b * 1024 + hw4];
    const float m = g_mean[b * CO_N + co];
    const float rs = g_rstd[b * CO_N + co];
    const float* cw = g_cwT + co * NCLS;
    const float* cb = g_cbT + co * NCLS;

    float4 o;
    o.x = (cv.x - m) * rs * cw[lb.x] + cb[lb.x];
    o.y = (cv.y - m) * rs * cw[lb.y] + cb[lb.y];
    o.z = (cv.z - m) * rs * cw[lb.z] + cb[lb.z];
    o.w = (cv.w - m) * rs * cw[lb.w] + cb[lb.w];
    ((float4*)out)[idx] = o;
}

// ---------------- launch ----------------
extern "C" void kernel_launch(void* const* d_in, const int* in_sizes, int n_in,
                              void* d_out, int out_size)
{
    const float* input       = (const float*)d_in[0];
    const float* style       = (const float*)d_in[1];
    const float* class_style = (const float*)d_in[2];
    const float* weight      = (const float*)d_in[3];
    const float* mod_w       = (const float*)d_in[4];
    const float* mod_b       = (const float*)d_in[5];
    const float* cw_w        = (const float*)d_in[6];
    const float* cw_b        = (const float*)d_in[7];
    const float* cb_w        = (const float*)d_in[8];
    const float* cb_b        = (const float*)d_in[9];
    const int*   label       = (const int*)d_in[10];
    float* out = (float*)d_out;

    eqlin_kernel<<<(BB * CI_N + 7) / 8, 256>>>(style, mod_w, mod_b, BB, CI_N, 1, CI_N, 0);
    eqlin_kernel<<<(NCLS * CO_N + 7) / 8, 256>>>(class_style, cw_w, cw_b, NCLS, CO_N, NCLS, 1, 1);
    eqlin_kernel<<<(NCLS * CO_N + 7) / 8, 256>>>(class_style, cb_w, cb_b, NCLS, CO_N, NCLS, 1, 2);

    uprep_kernel<<<(CO_N * CI_N + 255) / 256, 256>>>(weight);
    vprep_kernel<<<BB * 256, 256>>>(input);

    wgemm_kernel<<<16 * 8 * 32, 256>>>();

    outtrans_kernel<<<(CO_N * NT) / 256, 256>>>();
    stats_kernel<<<BB * CO_N, 256>>>();
    apply_kernel<<<(BB * CO_N * HWN) / 4 / 256, 256>>>(label, out);
}

// round 7
// speedup vs baseline: 13.5254x; 1.0652x over previous
#include <cuda_runtime.h>
#include <cuda_fp16.h>
#include <cstdint>

// Problem constants
#define BB    8
#define CI_N  512
#define CO_N  512
#define HWN   4096
#define NCLS  35
#define SDIM  512
#define NT    8192              // total output tiles: 8 b * 32*32

// ---------------- scratch (device globals) ----------------
__device__ float g_s[BB * CI_N];
__device__ float g_cwT[CO_N * NCLS];
__device__ float g_cbT[CO_N * NCLS];
__device__ __half g_U[(size_t)16 * CO_N * CI_N];          // fragment-ordered Winograd weights
__device__ uint32_t g_V[(size_t)16 * (CI_N / 2) * NT];    // half2(ci even, ci odd)
__device__ float g_M[(size_t)16 * CO_N * NT];             // GEMM results (fp32, 268MB)

// ---------------- helpers ----------------
__device__ __forceinline__ uint32_t smem_u32(const void* p) {
    uint32_t a;
    asm("{ .reg .u64 t; cvta.to.shared.u64 t, %1; cvt.u32.u64 %0, t; }" : "=r"(a) : "l"(p));
    return a;
}
__device__ __forceinline__ void cp_async16(uint32_t dst, const void* src) {
    asm volatile("cp.async.cg.shared.global [%0], [%1], 16;" :: "r"(dst), "l"(src) : "memory");
}
#define CP_COMMIT() asm volatile("cp.async.commit_group;" ::: "memory")
#define CP_WAIT(n)  asm volatile("cp.async.wait_group %0;" :: "n"(n) : "memory")

__device__ __forceinline__ void mma16(float* c, uint4 a, uint32_t b0, uint32_t b1) {
    asm volatile(
        "mma.sync.aligned.m16n8k16.row.col.f32.f16.f16.f32 "
        "{%0,%1,%2,%3}, {%4,%5,%6,%7}, {%8,%9}, {%0,%1,%2,%3};"
        : "+f"(c[0]), "+f"(c[1]), "+f"(c[2]), "+f"(c[3])
        : "r"(a.x), "r"(a.y), "r"(a.z), "r"(a.w), "r"(b0), "r"(b1));
}
__device__ __forceinline__ uint32_t pack_h2(float a, float b) {
    __half2 h = __floats2half2_rn(a, b);
    return *(uint32_t*)&h;
}

// ---------------- EqualLinear ----------------
__global__ void eqlin_kernel(const float* __restrict__ X, const float* __restrict__ W,
                             const float* __restrict__ bias,
                             int M, int N, int sj, int si, int which)
{
    int wg = (blockIdx.x * blockDim.x + threadIdx.x) >> 5;
    int lane = threadIdx.x & 31;
    if (wg >= M * N) return;
    int i = wg / N, j = wg - i * N;
    const float4* x4 = (const float4*)(X + (size_t)i * SDIM);
    const float4* w4 = (const float4*)(W + (size_t)j * SDIM);
    float acc = 0.f;
#pragma unroll
    for (int q = 0; q < 4; q++) {
        float4 a = x4[lane + q * 32], b = w4[lane + q * 32];
        acc += a.x * b.x + a.y * b.y + a.z * b.z + a.w * b.w;
    }
#pragma unroll
    for (int o = 16; o > 0; o >>= 1) acc += __shfl_xor_sync(0xffffffffu, acc, o);
    if (lane == 0) {
        float v = acc * 0.04419417382415922f + bias[j];
        float* dst = (which == 0) ? g_s : (which == 1) ? g_cwT : g_cbT;
        dst[j * sj + i * si] = v;
    }
}

// ---------------- U-prep: U = G g G^T per (co,ci), fragment-ordered fp16 ----------------
__global__ void uprep_kernel(const float* __restrict__ w)
{
    int idx = blockIdx.x * 256 + threadIdx.x;      // co*512 + ci
    if (idx >= CO_N * CI_N) return;
    int co = idx >> 9, ci = idx & 511;
    const float* gp = w + (size_t)idx * 9;
    float g0[3] = {gp[0], gp[1], gp[2]};
    float g1[3] = {gp[3], gp[4], gp[5]};
    float g2[3] = {gp[6], gp[7], gp[8]};
    float T[4][3], U[4][4];
#pragma unroll
    for (int c = 0; c < 3; c++) {
        T[0][c] = g0[c];
        T[1][c] = 0.5f * (g0[c] + g1[c] + g2[c]);
        T[2][c] = 0.5f * (g0[c] - g1[c] + g2[c]);
        T[3][c] = g2[c];
    }
#pragma unroll
    for (int r = 0; r < 4; r++) {
        U[r][0] = T[r][0];
        U[r][1] = 0.5f * (T[r][0] + T[r][1] + T[r][2]);
        U[r][2] = 0.5f * (T[r][0] - T[r][1] + T[r][2]);
        U[r][3] = T[r][2];
    }
    int cob = co >> 6;
    int c16 = ci >> 4;
    int mt = (co >> 4) & 3;
    int gg = co & 7;
    int j1 = (co >> 3) & 1;
    int t = (ci >> 1) & 3;
    int j0 = ci & 1;
    int j2 = (ci >> 3) & 1;
    int lane = (gg << 2) | t;
    int j = j0 | (j1 << 1) | (j2 << 2);
#pragma unroll
    for (int e = 0; e < 16; e++) {
        size_t addr = ((((size_t)e * 8 + cob) * 32 + c16) * 4 + mt) * 256 + lane * 8 + j;
        g_U[addr] = __float2half_rn(U[e >> 2][e & 3]);
    }
}

// ---------------- V-prep: V = B^T d B per 4x4 patch, style-scaled, half2 packed ----------------
__global__ void __launch_bounds__(256) vprep_kernel(const float* __restrict__ x)
{
    __shared__ float xs[2 * 66 * 66];
    const int tid = threadIdx.x;
    const int b = blockIdx.x >> 8;
    const int ci2 = blockIdx.x & 255;

    for (int i = tid; i < 2 * 66 * 66; i += 256) xs[i] = 0.f;
    __syncthreads();

    const float s0 = g_s[b * CI_N + 2 * ci2];
    const float s1 = g_s[b * CI_N + 2 * ci2 + 1];
    const float* x0 = x + ((size_t)b * CI_N + 2 * ci2) * HWN;
    const float* x1 = x0 + HWN;
    for (int i = tid; i < HWN; i += 256) {
        int r = i >> 6, c = i & 63;
        xs[(r + 1) * 66 + (c + 1)] = x0[i] * s0;
        xs[66 * 66 + (r + 1) * 66 + (c + 1)] = x1[i] * s1;
    }
    __syncthreads();

#pragma unroll 1
    for (int rep = 0; rep < 4; rep++) {
        int tpos = tid + rep * 256;
        int ty = tpos >> 5, tx = tpos & 31;
        float V2[2][4][4];
#pragma unroll
        for (int cin = 0; cin < 2; cin++) {
            const float* base = xs + cin * (66 * 66) + (2 * ty) * 66 + 2 * tx;
            float p[4][4];
#pragma unroll
            for (int r = 0; r < 4; r++)
#pragma unroll
                for (int c = 0; c < 4; c++) p[r][c] = base[r * 66 + c];
            float t1[4][4];
#pragma unroll
            for (int c = 0; c < 4; c++) {
                t1[0][c] = p[0][c] - p[2][c];
                t1[1][c] = p[1][c] + p[2][c];
                t1[2][c] = p[2][c] - p[1][c];
                t1[3][c] = p[1][c] - p[3][c];
            }
#pragma unroll
            for (int r = 0; r < 4; r++) {
                V2[cin][r][0] = t1[r][0] - t1[r][2];
                V2[cin][r][1] = t1[r][1] + t1[r][2];
                V2[cin][r][2] = t1[r][2] - t1[r][1];
                V2[cin][r][3] = t1[r][1] - t1[r][3];
            }
        }
        size_t n = (size_t)b * 1024 + tpos;
#pragma unroll
        for (int e = 0; e < 16; e++) {
            g_V[((size_t)e * 256 + ci2) * NT + n] =
                pack_h2(V2[0][e >> 2][e & 3], V2[1][e >> 2][e & 3]);
        }
    }
}

// ---------------- GEMM: M[e] = U[e] @ V[e]  (64co x 256n CTA tile) ----------------
#define BPITCH 264   // uint32 row pitch (264 % 32 == 8 -> conflict-free frag reads)

__device__ __forceinline__ void gstage(uint32_t ab, uint32_t bb, int e, int cob,
                                       int nb, int c, int tid)
{
    const __half* asrc = g_U + (((size_t)e * 8 + cob) * 32 + c) * 1024;
    if (tid < 128) cp_async16(ab + tid * 16, asrc + tid * 8);
    const uint32_t* bsrc = g_V + ((size_t)e * 256 + c * 8) * NT + nb * 256;
#pragma unroll
    for (int k = 0; k < 2; k++) {
        int idx = tid + k * 256;
        int r = idx >> 6, q = idx & 63;
        cp_async16(bb + (r * BPITCH + q * 4) * 4, bsrc + (size_t)r * NT + q * 4);
    }
}

__global__ void __launch_bounds__(256, 2) wgemm_kernel()
{
    __shared__ __align__(16) char smA[2][2048];
    __shared__ __align__(16) char smB[2][2 * BPITCH * 8 * 2];  // 8448B each

    const int tid = threadIdx.x;
    const int bx = blockIdx.x;
    const int nb = bx & 31, cob = (bx >> 5) & 7, e = bx >> 8;
    const int wid = tid >> 5, lane = tid & 31;
    const int wco = wid & 1, wn = wid >> 1;
    const int g = lane >> 2, t = lane & 3;

    const uint32_t ab0 = smem_u32(smA[0]), ab1 = smem_u32(smA[1]);
    const uint32_t bb0 = smem_u32(smB[0]), bb1 = smem_u32(smB[1]);

    float C[2][8][4];
#pragma unroll
    for (int m = 0; m < 2; m++)
#pragma unroll
        for (int tn = 0; tn < 8; tn++)
#pragma unroll
            for (int j = 0; j < 4; j++) C[m][tn][j] = 0.f;

    gstage(ab0, bb0, e, cob, nb, 0, tid); CP_COMMIT();
    gstage(ab1, bb1, e, cob, nb, 1, tid); CP_COMMIT();

    for (int c = 0; c < 32; c++) {
        const int buf = c & 1;
        CP_WAIT(1);
        __syncthreads();
        const uint4* abuf = (const uint4*)(buf ? smA[1] : smA[0]);
        const uint32_t* bbuf = (const uint32_t*)(buf ? smB[1] : smB[0]);

        uint4 A0 = abuf[(2 * wco + 0) * 32 + lane];
        uint4 A1 = abuf[(2 * wco + 1) * 32 + lane];
        const uint32_t* br0 = bbuf + t * BPITCH + wn * 64 + g;
        const uint32_t* br1 = bbuf + (t + 4) * BPITCH + wn * 64 + g;
#pragma unroll
        for (int tn = 0; tn < 8; tn++) {
            uint32_t b0 = br0[tn * 8];
            uint32_t b1 = br1[tn * 8];
            mma16(C[0][tn], A0, b0, b1);
            mma16(C[1][tn], A1, b0, b1);
        }
        __syncthreads();
        if (c + 2 < 32)
            gstage(buf ? ab1 : ab0, buf ? bb1 : bb0, e, cob, nb, c + 2, tid);
        CP_COMMIT();
    }

    // epilogue: write M fp32
#pragma unroll
    for (int m = 0; m < 2; m++) {
        int co = cob * 64 + wco * 32 + m * 16 + g;
        float* base = g_M + ((size_t)e * 512 + co) * NT + nb * 256 + wn * 64;
#pragma unroll
        for (int tn = 0; tn < 8; tn++) {
            int col = tn * 8 + 2 * t;
            *(float2*)(base + col) = make_float2(C[m][tn][0], C[m][tn][1]);
            *(float2*)(base + 8 * NT + col) = make_float2(C[m][tn][2], C[m][tn][3]);
        }
    }
}

// ---------------- fused: output transform + instance norm + CLADE apply ----------------
// one block per (b, co) channel; 256 threads, 4 tiles each
__global__ void __launch_bounds__(256) fuse_kernel(const int* __restrict__ label,
                                                   float* __restrict__ out)
{
    const int bc = blockIdx.x;            // b*512 + co
    const int b = bc >> 9, co = bc & 511;
    const int t = threadIdx.x;

    float Y[4][4];
    float s1 = 0.f, s2 = 0.f;

#pragma unroll
    for (int k = 0; k < 4; k++) {
        const size_t n = (size_t)b * 1024 + t + k * 256;
        float m[16];
#pragma unroll
        for (int e = 0; e < 16; e++)
            m[e] = g_M[((size_t)e * 512 + co) * NT + n];

        float t0[4], t1[4];
#pragma unroll
        for (int c = 0; c < 4; c++) {
            t0[c] = m[0 + c] + m[4 + c] + m[8 + c];
            t1[c] = m[4 + c] - m[8 + c] - m[12 + c];
        }
        float y00 = t0[0] + t0[1] + t0[2];
        float y01 = t0[1] - t0[2] - t0[3];
        float y10 = t1[0] + t1[1] + t1[2];
        float y11 = t1[1] - t1[2] - t1[3];
        Y[k][0] = y00; Y[k][1] = y01; Y[k][2] = y10; Y[k][3] = y11;
        s1 += (y00 + y01) + (y10 + y11);
        s2 += y00 * y00 + y01 * y01 + y10 * y10 + y11 * y11;
    }

    // block reduction for mean/var
#pragma unroll
    for (int o = 16; o > 0; o >>= 1) {
        s1 += __shfl_xor_sync(0xffffffffu, s1, o);
        s2 += __shfl_xor_sync(0xffffffffu, s2, o);
    }
    __shared__ float r1[8], r2[8];
    __shared__ float sh_mu, sh_rs;
    if ((t & 31) == 0) { r1[t >> 5] = s1; r2[t >> 5] = s2; }
    __syncthreads();
    if (t < 8) {
        s1 = r1[t]; s2 = r2[t];
#pragma unroll
        for (int o = 4; o > 0; o >>= 1) {
            s1 += __shfl_xor_sync(0xffu, s1, o);
            s2 += __shfl_xor_sync(0xffu, s2, o);
        }
        if (t == 0) {
            float mu = s1 * (1.f / 4096.f);
            float var = s2 * (1.f / 4096.f) - mu * mu;
            sh_mu = mu;
            sh_rs = rsqrtf(var + 1e-5f);
        }
    }
    __syncthreads();

    const float mu = sh_mu, rs = sh_rs;
    const float* cw = g_cwT + co * NCLS;
    const float* cb = g_cbT + co * NCLS;
    const int* lb = label + (size_t)b * HWN;
    float* ob = out + (size_t)bc * HWN;

#pragma unroll
    for (int k = 0; k < 4; k++) {
        int tpos = t + k * 256;
        int ty = tpos >> 5, tx = tpos & 31;
        int off = (2 * ty) * 64 + 2 * tx;
        int2 l0 = *(const int2*)(lb + off);
        int2 l1 = *(const int2*)(lb + off + 64);
        float2 o0, o1;
        o0.x = (Y[k][0] - mu) * rs * cw[l0.x] + cb[l0.x];
        o0.y = (Y[k][1] - mu) * rs * cw[l0.y] + cb[l0.y];
        o1.x = (Y[k][2] - mu) * rs * cw[l1.x] + cb[l1.x];
        o1.y = (Y[k][3] - mu) * rs * cw[l1.y] + cb[l1.y];
        *(float2*)(ob + off) = o0;
        *(float2*)(ob + off + 64) = o1;
    }
}

// ---------------- launch ----------------
extern "C" void kernel_launch(void* const* d_in, const int* in_sizes, int n_in,
                              void* d_out, int out_size)
{
    const float* input       = (const float*)d_in[0];
    const float* style       = (const float*)d_in[1];
    const float* class_style = (const float*)d_in[2];
    const float* weight      = (const float*)d_in[3];
    const float* mod_w       = (const float*)d_in[4];
    const float* mod_b       = (const float*)d_in[5];
    const float* cw_w        = (const float*)d_in[6];
    const float* cw_b        = (const float*)d_in[7];
    const float* cb_w        = (const float*)d_in[8];
    const float* cb_b        = (const float*)d_in[9];
    const int*   label       = (const int*)d_in[10];
    float* out = (float*)d_out;

    eqlin_kernel<<<(BB * CI_N + 7) / 8, 256>>>(style, mod_w, mod_b, BB, CI_N, 1, CI_N, 0);
    eqlin_kernel<<<(NCLS * CO_N + 7) / 8, 256>>>(class_style, cw_w, cw_b, NCLS, CO_N, NCLS, 1, 1);
    eqlin_kernel<<<(NCLS * CO_N + 7) / 8, 256>>>(class_style, cb_w, cb_b, NCLS, CO_N, NCLS, 1, 2);

    uprep_kernel<<<(CO_N * CI_N + 255) / 256, 256>>>(weight);
    vprep_kernel<<<BB * 256, 256>>>(input);

    wgemm_kernel<<<16 * 8 * 32, 256>>>();

    fuse_kernel<<<BB * CO_N, 256>>>(label, out);
}

// round 8
// speedup vs baseline: 13.6799x; 1.0114x over previous
#include <cuda_runtime.h>
#include <cuda_fp16.h>
#include <cstdint>

// Problem constants
#define BB    8
#define CI_N  512
#define CO_N  512
#define HWN   4096
#define NCLS  35
#define SDIM  512
#define NT    8192              // total output tiles: 8 b * 32*32

// ---------------- scratch (device globals) ----------------
__device__ float g_s[BB * CI_N];
__device__ float g_cwT[CO_N * NCLS];
__device__ float g_cbT[CO_N * NCLS];
__device__ __half g_U[(size_t)16 * CO_N * CI_N];          // fragment-ordered Winograd weights
__device__ uint32_t g_V[(size_t)16 * (CI_N / 2) * NT];    // half2(ci even, ci odd)
__device__ float g_M[(size_t)16 * CO_N * NT];             // GEMM results (fp32, 268MB)

// ---------------- helpers ----------------
__device__ __forceinline__ uint32_t smem_u32(const void* p) {
    uint32_t a;
    asm("{ .reg .u64 t; cvta.to.shared.u64 t, %1; cvt.u32.u64 %0, t; }" : "=r"(a) : "l"(p));
    return a;
}
__device__ __forceinline__ void cp_async16(uint32_t dst, const void* src) {
    asm volatile("cp.async.cg.shared.global [%0], [%1], 16;" :: "r"(dst), "l"(src) : "memory");
}
#define CP_COMMIT() asm volatile("cp.async.commit_group;" ::: "memory")
#define CP_WAIT(n)  asm volatile("cp.async.wait_group %0;" :: "n"(n) : "memory")

__device__ __forceinline__ void mma16(float* c, uint4 a, uint32_t b0, uint32_t b1) {
    asm volatile(
        "mma.sync.aligned.m16n8k16.row.col.f32.f16.f16.f32 "
        "{%0,%1,%2,%3}, {%4,%5,%6,%7}, {%8,%9}, {%0,%1,%2,%3};"
        : "+f"(c[0]), "+f"(c[1]), "+f"(c[2]), "+f"(c[3])
        : "r"(a.x), "r"(a.y), "r"(a.z), "r"(a.w), "r"(b0), "r"(b1));
}
__device__ __forceinline__ uint32_t pack_h2(float a, float b) {
    __half2 h = __floats2half2_rn(a, b);
    return *(uint32_t*)&h;
}

// ---------------- EqualLinear ----------------
__global__ void eqlin_kernel(const float* __restrict__ X, const float* __restrict__ W,
                             const float* __restrict__ bias,
                             int M, int N, int sj, int si, int which)
{
    int wg = (blockIdx.x * blockDim.x + threadIdx.x) >> 5;
    int lane = threadIdx.x & 31;
    if (wg >= M * N) return;
    int i = wg / N, j = wg - i * N;
    const float4* x4 = (const float4*)(X + (size_t)i * SDIM);
    const float4* w4 = (const float4*)(W + (size_t)j * SDIM);
    float acc = 0.f;
#pragma unroll
    for (int q = 0; q < 4; q++) {
        float4 a = x4[lane + q * 32], b = w4[lane + q * 32];
        acc += a.x * b.x + a.y * b.y + a.z * b.z + a.w * b.w;
    }
#pragma unroll
    for (int o = 16; o > 0; o >>= 1) acc += __shfl_xor_sync(0xffffffffu, acc, o);
    if (lane == 0) {
        float v = acc * 0.04419417382415922f + bias[j];
        float* dst = (which == 0) ? g_s : (which == 1) ? g_cwT : g_cbT;
        dst[j * sj + i * si] = v;
    }
}

// ---------------- U-prep: U = G g G^T per (co,ci), fragment-ordered fp16 ----------------
__global__ void uprep_kernel(const float* __restrict__ w)
{
    int idx = blockIdx.x * 256 + threadIdx.x;      // co*512 + ci
    if (idx >= CO_N * CI_N) return;
    int co = idx >> 9, ci = idx & 511;
    const float* gp = w + (size_t)idx * 9;
    float g0[3] = {gp[0], gp[1], gp[2]};
    float g1[3] = {gp[3], gp[4], gp[5]};
    float g2[3] = {gp[6], gp[7], gp[8]};
    float T[4][3], U[4][4];
#pragma unroll
    for (int c = 0; c < 3; c++) {
        T[0][c] = g0[c];
        T[1][c] = 0.5f * (g0[c] + g1[c] + g2[c]);
        T[2][c] = 0.5f * (g0[c] - g1[c] + g2[c]);
        T[3][c] = g2[c];
    }
#pragma unroll
    for (int r = 0; r < 4; r++) {
        U[r][0] = T[r][0];
        U[r][1] = 0.5f * (T[r][0] + T[r][1] + T[r][2]);
        U[r][2] = 0.5f * (T[r][0] - T[r][1] + T[r][2]);
        U[r][3] = T[r][2];
    }
    int cob = co >> 6;
    int c16 = ci >> 4;
    int mt = (co >> 4) & 3;
    int gg = co & 7;
    int j1 = (co >> 3) & 1;
    int t = (ci >> 1) & 3;
    int j0 = ci & 1;
    int j2 = (ci >> 3) & 1;
    int lane = (gg << 2) | t;
    int j = j0 | (j1 << 1) | (j2 << 2);
#pragma unroll
    for (int e = 0; e < 16; e++) {
        size_t addr = ((((size_t)e * 8 + cob) * 32 + c16) * 4 + mt) * 256 + lane * 8 + j;
        g_U[addr] = __float2half_rn(U[e >> 2][e & 3]);
    }
}

// ---------------- V-prep: V = B^T d B per 4x4 patch, style-scaled, half2 packed ----------------
__global__ void __launch_bounds__(256) vprep_kernel(const float* __restrict__ x)
{
    __shared__ float xs[2 * 66 * 66];
    const int tid = threadIdx.x;
    const int b = blockIdx.x >> 8;
    const int ci2 = blockIdx.x & 255;

    for (int i = tid; i < 2 * 66 * 66; i += 256) xs[i] = 0.f;
    __syncthreads();

    const float s0 = g_s[b * CI_N + 2 * ci2];
    const float s1 = g_s[b * CI_N + 2 * ci2 + 1];
    const float* x0 = x + ((size_t)b * CI_N + 2 * ci2) * HWN;
    const float* x1 = x0 + HWN;
    for (int i = tid; i < HWN; i += 256) {
        int r = i >> 6, c = i & 63;
        xs[(r + 1) * 66 + (c + 1)] = x0[i] * s0;
        xs[66 * 66 + (r + 1) * 66 + (c + 1)] = x1[i] * s1;
    }
    __syncthreads();

#pragma unroll 1
    for (int rep = 0; rep < 4; rep++) {
        int tpos = tid + rep * 256;
        int ty = tpos >> 5, tx = tpos & 31;
        float V2[2][4][4];
#pragma unroll
        for (int cin = 0; cin < 2; cin++) {
            const float* base = xs + cin * (66 * 66) + (2 * ty) * 66 + 2 * tx;
            float p[4][4];
#pragma unroll
            for (int r = 0; r < 4; r++)
#pragma unroll
                for (int c = 0; c < 4; c++) p[r][c] = base[r * 66 + c];
            float t1[4][4];
#pragma unroll
            for (int c = 0; c < 4; c++) {
                t1[0][c] = p[0][c] - p[2][c];
                t1[1][c] = p[1][c] + p[2][c];
                t1[2][c] = p[2][c] - p[1][c];
                t1[3][c] = p[1][c] - p[3][c];
            }
#pragma unroll
            for (int r = 0; r < 4; r++) {
                V2[cin][r][0] = t1[r][0] - t1[r][2];
                V2[cin][r][1] = t1[r][1] + t1[r][2];
                V2[cin][r][2] = t1[r][2] - t1[r][1];
                V2[cin][r][3] = t1[r][1] - t1[r][3];
            }
        }
        size_t n = (size_t)b * 1024 + tpos;
#pragma unroll
        for (int e = 0; e < 16; e++) {
            g_V[((size_t)e * 256 + ci2) * NT + n] =
                pack_h2(V2[0][e >> 2][e & 3], V2[1][e >> 2][e & 3]);
        }
    }
}

// ---------------- GEMM: M[e] = U[e] @ V[e]  (64co x 256n CTA tile) ----------------
#define BPITCH 264   // uint32 row pitch (264 % 32 == 8 -> conflict-free frag reads)

__device__ __forceinline__ void gstage(uint32_t ab, uint32_t bb, int e, int cob,
                                       int nb, int c, int tid)
{
    const __half* asrc = g_U + (((size_t)e * 8 + cob) * 32 + c) * 1024;
    if (tid < 128) cp_async16(ab + tid * 16, asrc + tid * 8);
    const uint32_t* bsrc = g_V + ((size_t)e * 256 + c * 8) * NT + nb * 256;
#pragma unroll
    for (int k = 0; k < 2; k++) {
        int idx = tid + k * 256;
        int r = idx >> 6, q = idx & 63;
        cp_async16(bb + (r * BPITCH + q * 4) * 4, bsrc + (size_t)r * NT + q * 4);
    }
}

__global__ void __launch_bounds__(256, 2) wgemm_kernel()
{
    __shared__ __align__(16) char smA[2][2048];
    __shared__ __align__(16) char smB[2][2 * BPITCH * 8 * 2];  // 8448B each

    const int tid = threadIdx.x;
    const int bx = blockIdx.x;
    const int nb = bx & 31, cob = (bx >> 5) & 7, e = bx >> 8;
    const int wid = tid >> 5, lane = tid & 31;
    const int wco = wid & 1, wn = wid >> 1;
    const int g = lane >> 2, t = lane & 3;

    const uint32_t ab0 = smem_u32(smA[0]), ab1 = smem_u32(smA[1]);
    const uint32_t bb0 = smem_u32(smB[0]), bb1 = smem_u32(smB[1]);

    float C[2][8][4];
#pragma unroll
    for (int m = 0; m < 2; m++)
#pragma unroll
        for (int tn = 0; tn < 8; tn++)
#pragma unroll
            for (int j = 0; j < 4; j++) C[m][tn][j] = 0.f;

    gstage(ab0, bb0, e, cob, nb, 0, tid); CP_COMMIT();
    gstage(ab1, bb1, e, cob, nb, 1, tid); CP_COMMIT();

    for (int c = 0; c < 32; c++) {
        const int buf = c & 1;
        CP_WAIT(1);
        __syncthreads();
        const uint4* abuf = (const uint4*)(buf ? smA[1] : smA[0]);
        const uint32_t* bbuf = (const uint32_t*)(buf ? smB[1] : smB[0]);

        uint4 A0 = abuf[(2 * wco + 0) * 32 + lane];
        uint4 A1 = abuf[(2 * wco + 1) * 32 + lane];
        const uint32_t* br0 = bbuf + t * BPITCH + wn * 64 + g;
        const uint32_t* br1 = bbuf + (t + 4) * BPITCH + wn * 64 + g;
#pragma unroll
        for (int tn = 0; tn < 8; tn++) {
            uint32_t b0 = br0[tn * 8];
            uint32_t b1 = br1[tn * 8];
            mma16(C[0][tn], A0, b0, b1);
            mma16(C[1][tn], A1, b0, b1);
        }
        __syncthreads();
        if (c + 2 < 32)
            gstage(buf ? ab1 : ab0, buf ? bb1 : bb0, e, cob, nb, c + 2, tid);
        CP_COMMIT();
    }

    // epilogue: write M fp32
#pragma unroll
    for (int m = 0; m < 2; m++) {
        int co = cob * 64 + wco * 32 + m * 16 + g;
        float* base = g_M + ((size_t)e * 512 + co) * NT + nb * 256 + wn * 64;
#pragma unroll
        for (int tn = 0; tn < 8; tn++) {
            int col = tn * 8 + 2 * t;
            *(float2*)(base + col) = make_float2(C[m][tn][0], C[m][tn][1]);
            *(float2*)(base + 8 * NT + col) = make_float2(C[m][tn][2], C[m][tn][3]);
        }
    }
}

// ---------------- fused: output transform + instance norm + CLADE apply ----------------
// one block per (b, co) channel; 256 threads, 4 tiles each
__global__ void __launch_bounds__(256) fuse_kernel(const int* __restrict__ label,
                                                   float* __restrict__ out)
{
    const int bc = blockIdx.x;            // b*512 + co
    const int b = bc >> 9, co = bc & 511;
    const int t = threadIdx.x;

    float Y[4][4];
    float s1 = 0.f, s2 = 0.f;

#pragma unroll
    for (int k = 0; k < 4; k++) {
        const size_t n = (size_t)b * 1024 + t + k * 256;
        float m[16];
#pragma unroll
        for (int e = 0; e < 16; e++)
            m[e] = g_M[((size_t)e * 512 + co) * NT + n];

        float t0[4], t1[4];
#pragma unroll
        for (int c = 0; c < 4; c++) {
            t0[c] = m[0 + c] + m[4 + c] + m[8 + c];
            t1[c] = m[4 + c] - m[8 + c] - m[12 + c];
        }
        float y00 = t0[0] + t0[1] + t0[2];
        float y01 = t0[1] - t0[2] - t0[3];
        float y10 = t1[0] + t1[1] + t1[2];
        float y11 = t1[1] - t1[2] - t1[3];
        Y[k][0] = y00; Y[k][1] = y01; Y[k][2] = y10; Y[k][3] = y11;
        s1 += (y00 + y01) + (y10 + y11);
        s2 += y00 * y00 + y01 * y01 + y10 * y10 + y11 * y11;
    }

    // block reduction for mean/var
#pragma unroll
    for (int o = 16; o > 0; o >>= 1) {
        s1 += __shfl_xor_sync(0xffffffffu, s1, o);
        s2 += __shfl_xor_sync(0xffffffffu, s2, o);
    }
    __shared__ float r1[8], r2[8];
    __shared__ float sh_mu, sh_rs;
    if ((t & 31) == 0) { r1[t >> 5] = s1; r2[t >> 5] = s2; }
    __syncthreads();
    if (t < 8) {
        s1 = r1[t]; s2 = r2[t];
#pragma unroll
        for (int o = 4; o > 0; o >>= 1) {
            s1 += __shfl_xor_sync(0xffu, s1, o);
            s2 += __shfl_xor_sync(0xffu, s2, o);
        }
        if (t == 0) {
            float mu = s1 * (1.f / 4096.f);
            float var = s2 * (1.f / 4096.f) - mu * mu;
            sh_mu = mu;
            sh_rs = rsqrtf(var + 1e-5f);
        }
    }
    __syncthreads();

    const float mu = sh_mu, rs = sh_rs;
    const float* cw = g_cwT + co * NCLS;
    const float* cb = g_cbT + co * NCLS;
    const int* lb = label + (size_t)b * HWN;
    float* ob = out + (size_t)bc * HWN;

#pragma unroll
    for (int k = 0; k < 4; k++) {
        int tpos = t + k * 256;
        int ty = tpos >> 5, tx = tpos & 31;
        int off = (2 * ty) * 64 + 2 * tx;
        int2 l0 = *(const int2*)(lb + off);
        int2 l1 = *(const int2*)(lb + off + 64);
        float2 o0, o1;
        o0.x = (Y[k][0] - mu) * rs * cw[l0.x] + cb[l0.x];
        o0.y = (Y[k][1] - mu) * rs * cw[l0.y] + cb[l0.y];
        o1.x = (Y[k][2] - mu) * rs * cw[l1.x] + cb[l1.x];
        o1.y = (Y[k][3] - mu) * rs * cw[l1.y] + cb[l1.y];
        *(float2*)(ob + off) = o0;
        *(float2*)(ob + off + 64) = o1;
    }
}

// ---------------- launch ----------------
extern "C" void kernel_launch(void* const* d_in, const int* in_sizes, int n_in,
                              void* d_out, int out_size)
{
    const float* input       = (const float*)d_in[0];
    const float* style       = (const float*)d_in[1];
    const float* class_style = (const float*)d_in[2];
    const float* weight      = (const float*)d_in[3];
    const float* mod_w       = (const float*)d_in[4];
    const float* mod_b       = (const float*)d_in[5];
    const float* cw_w        = (const float*)d_in[6];
    const float* cw_b        = (const float*)d_in[7];
    const float* cb_w        = (const float*)d_in[8];
    const float* cb_b        = (const float*)d_in[9];
    const int*   label       = (const int*)d_in[10];
    float* out = (float*)d_out;

    eqlin_kernel<<<(BB * CI_N + 7) / 8, 256>>>(style, mod_w, mod_b, BB, CI_N, 1, CI_N, 0);
    eqlin_kernel<<<(NCLS * CO_N + 7) / 8, 256>>>(class_style, cw_w, cw_b, NCLS, CO_N, NCLS, 1, 1);
    eqlin_kernel<<<(NCLS * CO_N + 7) / 8, 256>>>(class_style, cb_w, cb_b, NCLS, CO_N, NCLS, 1, 2);

    uprep_kernel<<<(CO_N * CI_N + 255) / 256, 256>>>(weight);
    vprep_kernel<<<BB * 256, 256>>>(input);

    wgemm_kernel<<<16 * 8 * 32, 256>>>();

    fuse_kernel<<<BB * CO_N, 256>>>(label, out);
}

// round 9
// speedup vs baseline: 14.3606x; 1.0498x over previous
#include <cuda_runtime.h>
#include <cuda_fp16.h>
#include <cstdint>

// Problem constants
#define BB    8
#define CI_N  512
#define CO_N  512
#define HWN   4096
#define NCLS  35
#define SDIM  512
#define NT    8192              // total output tiles: 8 b * 32*32

// ---------------- scratch (device globals) ----------------
__device__ float g_s[BB * CI_N];
__device__ float g_cwT[CO_N * NCLS];
__device__ float g_cbT[CO_N * NCLS];
__device__ __half g_U[(size_t)16 * CO_N * CI_N];          // fragment-ordered Winograd weights
__device__ uint32_t g_V[(size_t)16 * (CI_N / 2) * NT];    // half2(ci even, ci odd)
__device__ __half g_Mh[(size_t)16 * CO_N * NT];           // GEMM results (fp16, 134MB)

// ---------------- helpers ----------------
__device__ __forceinline__ uint32_t smem_u32(const void* p) {
    uint32_t a;
    asm("{ .reg .u64 t; cvta.to.shared.u64 t, %1; cvt.u32.u64 %0, t; }" : "=r"(a) : "l"(p));
    return a;
}
__device__ __forceinline__ void cp_async16(uint32_t dst, const void* src) {
    asm volatile("cp.async.cg.shared.global [%0], [%1], 16;" :: "r"(dst), "l"(src) : "memory");
}
#define CP_COMMIT() asm volatile("cp.async.commit_group;" ::: "memory")
#define CP_WAIT(n)  asm volatile("cp.async.wait_group %0;" :: "n"(n) : "memory")

__device__ __forceinline__ void mma16(float* c, uint4 a, uint32_t b0, uint32_t b1) {
    asm volatile(
        "mma.sync.aligned.m16n8k16.row.col.f32.f16.f16.f32 "
        "{%0,%1,%2,%3}, {%4,%5,%6,%7}, {%8,%9}, {%0,%1,%2,%3};"
        : "+f"(c[0]), "+f"(c[1]), "+f"(c[2]), "+f"(c[3])
        : "r"(a.x), "r"(a.y), "r"(a.z), "r"(a.w), "r"(b0), "r"(b1));
}
__device__ __forceinline__ uint32_t pack_h2(float a, float b) {
    __half2 h = __floats2half2_rn(a, b);
    return *(uint32_t*)&h;
}

// ---------------- EqualLinear (all three jobs in one launch) ----------------
// job 0: style -> g_s          (M=8,  N=512, dst[j + i*512])
// job 1: class_style -> g_cwT  (M=35, N=512, dst[j*35 + i])
// job 2: class_style -> g_cbT  (M=35, N=512, dst[j*35 + i])
#define EQL_W0 4096
#define EQL_W1 17920
__global__ void eqlin_all_kernel(const float* __restrict__ style,
                                 const float* __restrict__ class_style,
                                 const float* __restrict__ mod_w, const float* __restrict__ mod_b,
                                 const float* __restrict__ cw_w, const float* __restrict__ cw_b,
                                 const float* __restrict__ cb_w, const float* __restrict__ cb_b)
{
    int wg = (blockIdx.x * blockDim.x + threadIdx.x) >> 5;
    int lane = threadIdx.x & 31;
    const float *X, *W, *bias;
    float* dst;
    int i, j, sj, si;
    if (wg < EQL_W0) {
        i = wg >> 9; j = wg & 511;
        X = style; W = mod_w; bias = mod_b; dst = g_s; sj = 1; si = 512;
    } else if (wg < EQL_W0 + EQL_W1) {
        int r = wg - EQL_W0;
        i = r / 512; j = r & 511;
        X = class_style; W = cw_w; bias = cw_b; dst = g_cwT; sj = NCLS; si = 1;
    } else if (wg < EQL_W0 + 2 * EQL_W1) {
        int r = wg - EQL_W0 - EQL_W1;
        i = r / 512; j = r & 511;
        X = class_style; W = cb_w; bias = cb_b; dst = g_cbT; sj = NCLS; si = 1;
    } else return;

    const float4* x4 = (const float4*)(X + (size_t)i * SDIM);
    const float4* w4 = (const float4*)(W + (size_t)j * SDIM);
    float acc = 0.f;
#pragma unroll
    for (int q = 0; q < 4; q++) {
        float4 a = x4[lane + q * 32], b = w4[lane + q * 32];
        acc += a.x * b.x + a.y * b.y + a.z * b.z + a.w * b.w;
    }
#pragma unroll
    for (int o = 16; o > 0; o >>= 1) acc += __shfl_xor_sync(0xffffffffu, acc, o);
    if (lane == 0)
        dst[j * sj + i * si] = acc * 0.04419417382415922f + bias[j];
}

// ---------------- U-prep: U = G g G^T per (co,ci), fragment-ordered fp16 ----------------
__global__ void uprep_kernel(const float* __restrict__ w)
{
    int idx = blockIdx.x * 256 + threadIdx.x;      // co*512 + ci
    if (idx >= CO_N * CI_N) return;
    int co = idx >> 9, ci = idx & 511;
    const float* gp = w + (size_t)idx * 9;
    float g0[3] = {gp[0], gp[1], gp[2]};
    float g1[3] = {gp[3], gp[4], gp[5]};
    float g2[3] = {gp[6], gp[7], gp[8]};
    float T[4][3], U[4][4];
#pragma unroll
    for (int c = 0; c < 3; c++) {
        T[0][c] = g0[c];
        T[1][c] = 0.5f * (g0[c] + g1[c] + g2[c]);
        T[2][c] = 0.5f * (g0[c] - g1[c] + g2[c]);
        T[3][c] = g2[c];
    }
#pragma unroll
    for (int r = 0; r < 4; r++) {
        U[r][0] = T[r][0];
        U[r][1] = 0.5f * (T[r][0] + T[r][1] + T[r][2]);
        U[r][2] = 0.5f * (T[r][0] - T[r][1] + T[r][2]);
        U[r][3] = T[r][2];
    }
    int cob = co >> 6;
    int c16 = ci >> 4;
    int mt = (co >> 4) & 3;
    int gg = co & 7;
    int j1 = (co >> 3) & 1;
    int t = (ci >> 1) & 3;
    int j0 = ci & 1;
    int j2 = (ci >> 3) & 1;
    int lane = (gg << 2) | t;
    int j = j0 | (j1 << 1) | (j2 << 2);
#pragma unroll
    for (int e = 0; e < 16; e++) {
        size_t addr = ((((size_t)e * 8 + cob) * 32 + c16) * 4 + mt) * 256 + lane * 8 + j;
        g_U[addr] = __float2half_rn(U[e >> 2][e & 3]);
    }
}

// ---------------- V-prep: V = B^T d B per 4x4 patch, style-scaled, half2 packed ----------------
__global__ void __launch_bounds__(256) vprep_kernel(const float* __restrict__ x)
{
    __shared__ float xs[2 * 66 * 66];
    const int tid = threadIdx.x;
    const int b = blockIdx.x >> 8;
    const int ci2 = blockIdx.x & 255;

    for (int i = tid; i < 2 * 66 * 66; i += 256) xs[i] = 0.f;
    __syncthreads();

    const float s0 = g_s[b * CI_N + 2 * ci2];
    const float s1 = g_s[b * CI_N + 2 * ci2 + 1];
    const float* x0 = x + ((size_t)b * CI_N + 2 * ci2) * HWN;
    const float* x1 = x0 + HWN;
    for (int i = tid; i < HWN; i += 256) {
        int r = i >> 6, c = i & 63;
        xs[(r + 1) * 66 + (c + 1)] = x0[i] * s0;
        xs[66 * 66 + (r + 1) * 66 + (c + 1)] = x1[i] * s1;
    }
    __syncthreads();

#pragma unroll 1
    for (int rep = 0; rep < 4; rep++) {
        int tpos = tid + rep * 256;
        int ty = tpos >> 5, tx = tpos & 31;
        float V2[2][4][4];
#pragma unroll
        for (int cin = 0; cin < 2; cin++) {
            const float* base = xs + cin * (66 * 66) + (2 * ty) * 66 + 2 * tx;
            float p[4][4];
#pragma unroll
            for (int r = 0; r < 4; r++)
#pragma unroll
                for (int c = 0; c < 4; c++) p[r][c] = base[r * 66 + c];
            float t1[4][4];
#pragma unroll
            for (int c = 0; c < 4; c++) {
                t1[0][c] = p[0][c] - p[2][c];
                t1[1][c] = p[1][c] + p[2][c];
                t1[2][c] = p[2][c] - p[1][c];
                t1[3][c] = p[1][c] - p[3][c];
            }
#pragma unroll
            for (int r = 0; r < 4; r++) {
                V2[cin][r][0] = t1[r][0] - t1[r][2];
                V2[cin][r][1] = t1[r][1] + t1[r][2];
                V2[cin][r][2] = t1[r][2] - t1[r][1];
                V2[cin][r][3] = t1[r][1] - t1[r][3];
            }
        }
        size_t n = (size_t)b * 1024 + tpos;
#pragma unroll
        for (int e = 0; e < 16; e++) {
            g_V[((size_t)e * 256 + ci2) * NT + n] =
                pack_h2(V2[0][e >> 2][e & 3], V2[1][e >> 2][e & 3]);
        }
    }
}

// ---------------- GEMM: M[e] = U[e] @ V[e]  (64co x 256n CTA tile) ----------------
#define BPITCH 264   // uint32 row pitch (264 % 32 == 8 -> conflict-free frag reads)

__device__ __forceinline__ void gstage(uint32_t ab, uint32_t bb, int e, int cob,
                                       int nb, int c, int tid)
{
    const __half* asrc = g_U + (((size_t)e * 8 + cob) * 32 + c) * 1024;
    if (tid < 128) cp_async16(ab + tid * 16, asrc + tid * 8);
    const uint32_t* bsrc = g_V + ((size_t)e * 256 + c * 8) * NT + nb * 256;
#pragma unroll
    for (int k = 0; k < 2; k++) {
        int idx = tid + k * 256;
        int r = idx >> 6, q = idx & 63;
        cp_async16(bb + (r * BPITCH + q * 4) * 4, bsrc + (size_t)r * NT + q * 4);
    }
}

__global__ void __launch_bounds__(256, 2) wgemm_kernel()
{
    __shared__ __align__(16) char smA[2][2048];
    __shared__ __align__(16) char smB[2][2 * BPITCH * 8 * 2];  // 8448B each

    const int tid = threadIdx.x;
    const int bx = blockIdx.x;
    const int nb = bx & 31, cob = (bx >> 5) & 7, e = bx >> 8;
    const int wid = tid >> 5, lane = tid & 31;
    const int wco = wid & 1, wn = wid >> 1;
    const int g = lane >> 2, t = lane & 3;

    const uint32_t ab0 = smem_u32(smA[0]), ab1 = smem_u32(smA[1]);
    const uint32_t bb0 = smem_u32(smB[0]), bb1 = smem_u32(smB[1]);

    float C[2][8][4];
#pragma unroll
    for (int m = 0; m < 2; m++)
#pragma unroll
        for (int tn = 0; tn < 8; tn++)
#pragma unroll
            for (int j = 0; j < 4; j++) C[m][tn][j] = 0.f;

    gstage(ab0, bb0, e, cob, nb, 0, tid); CP_COMMIT();
    gstage(ab1, bb1, e, cob, nb, 1, tid); CP_COMMIT();

    for (int c = 0; c < 32; c++) {
        const int buf = c & 1;
        CP_WAIT(1);
        __syncthreads();
        const uint4* abuf = (const uint4*)(buf ? smA[1] : smA[0]);
        const uint32_t* bbuf = (const uint32_t*)(buf ? smB[1] : smB[0]);

        uint4 A0 = abuf[(2 * wco + 0) * 32 + lane];
        uint4 A1 = abuf[(2 * wco + 1) * 32 + lane];
        const uint32_t* br0 = bbuf + t * BPITCH + wn * 64 + g;
        const uint32_t* br1 = bbuf + (t + 4) * BPITCH + wn * 64 + g;
#pragma unroll
        for (int tn = 0; tn < 8; tn++) {
            uint32_t b0 = br0[tn * 8];
            uint32_t b1 = br1[tn * 8];
            mma16(C[0][tn], A0, b0, b1);
            mma16(C[1][tn], A1, b0, b1);
        }
        __syncthreads();
        if (c + 2 < 32)
            gstage(buf ? ab1 : ab0, buf ? bb1 : bb0, e, cob, nb, c + 2, tid);
        CP_COMMIT();
    }

    // epilogue: write M fp16 (half2 pairs: C[.][tn][0,1] and [2,3] are adjacent cols)
#pragma unroll
    for (int m = 0; m < 2; m++) {
        int co = cob * 64 + wco * 32 + m * 16 + g;
        __half* base = g_Mh + ((size_t)e * 512 + co) * NT + nb * 256 + wn * 64;
#pragma unroll
        for (int tn = 0; tn < 8; tn++) {
            int col = tn * 8 + 2 * t;
            *(uint32_t*)(base + col) = pack_h2(C[m][tn][0], C[m][tn][1]);
            *(uint32_t*)(base + 8 * NT + col) = pack_h2(C[m][tn][2], C[m][tn][3]);
        }
    }
}

// ---------------- fused: output transform + instance norm + CLADE apply ----------------
__global__ void __launch_bounds__(256) fuse_kernel(const int* __restrict__ label,
                                                   float* __restrict__ out)
{
    const int bc = blockIdx.x;            // b*512 + co
    const int b = bc >> 9, co = bc & 511;
    const int t = threadIdx.x;

    float Y[4][4];
    float s1 = 0.f, s2 = 0.f;

#pragma unroll
    for (int k = 0; k < 4; k++) {
        const size_t n = (size_t)b * 1024 + t + k * 256;
        float m[16];
#pragma unroll
        for (int e = 0; e < 16; e++)
            m[e] = __half2float(g_Mh[((size_t)e * 512 + co) * NT + n]);

        float t0[4], t1[4];
#pragma unroll
        for (int c = 0; c < 4; c++) {
            t0[c] = m[0 + c] + m[4 + c] + m[8 + c];
            t1[c] = m[4 + c] - m[8 + c] - m[12 + c];
        }
        float y00 = t0[0] + t0[1] + t0[2];
        float y01 = t0[1] - t0[2] - t0[3];
        float y10 = t1[0] + t1[1] + t1[2];
        float y11 = t1[1] - t1[2] - t1[3];
        Y[k][0] = y00; Y[k][1] = y01; Y[k][2] = y10; Y[k][3] = y11;
        s1 += (y00 + y01) + (y10 + y11);
        s2 += y00 * y00 + y01 * y01 + y10 * y10 + y11 * y11;
    }

#pragma unroll
    for (int o = 16; o > 0; o >>= 1) {
        s1 += __shfl_xor_sync(0xffffffffu, s1, o);
        s2 += __shfl_xor_sync(0xffffffffu, s2, o);
    }
    __shared__ float r1[8], r2[8];
    __shared__ float sh_mu, sh_rs;
    if ((t & 31) == 0) { r1[t >> 5] = s1; r2[t >> 5] = s2; }
    __syncthreads();
    if (t < 8) {
        s1 = r1[t]; s2 = r2[t];
#pragma unroll
        for (int o = 4; o > 0; o >>= 1) {
            s1 += __shfl_xor_sync(0xffu, s1, o);
            s2 += __shfl_xor_sync(0xffu, s2, o);
        }
        if (t == 0) {
            float mu = s1 * (1.f / 4096.f);
            float var = s2 * (1.f / 4096.f) - mu * mu;
            sh_mu = mu;
            sh_rs = rsqrtf(var + 1e-5f);
        }
    }
    __syncthreads();

    const float mu = sh_mu, rs = sh_rs;
    const float* cw = g_cwT + co * NCLS;
    const float* cb = g_cbT + co * NCLS;
    const int* lb = label + (size_t)b * HWN;
    float* ob = out + (size_t)bc * HWN;

#pragma unroll
    for (int k = 0; k < 4; k++) {
        int tpos = t + k * 256;
        int ty = tpos >> 5, tx = tpos & 31;
        int off = (2 * ty) * 64 + 2 * tx;
        int2 l0 = *(const int2*)(lb + off);
        int2 l1 = *(const int2*)(lb + off + 64);
        float2 o0, o1;
        o0.x = (Y[k][0] - mu) * rs * cw[l0.x] + cb[l0.x];
        o0.y = (Y[k][1] - mu) * rs * cw[l0.y] + cb[l0.y];
        o1.x = (Y[k][2] - mu) * rs * cw[l1.x] + cb[l1.x];
        o1.y = (Y[k][3] - mu) * rs * cw[l1.y] + cb[l1.y];
        *(float2*)(ob + off) = o0;
        *(float2*)(ob + off + 64) = o1;
    }
}

// ---------------- launch ----------------
extern "C" void kernel_launch(void* const* d_in, const int* in_sizes, int n_in,
                              void* d_out, int out_size)
{
    const float* input       = (const float*)d_in[0];
    const float* style       = (const float*)d_in[1];
    const float* class_style = (const float*)d_in[2];
    const float* weight      = (const float*)d_in[3];
    const float* mod_w       = (const float*)d_in[4];
    const float* mod_b       = (const float*)d_in[5];
    const float* cw_w        = (const float*)d_in[6];
    const float* cw_b        = (const float*)d_in[7];
    const float* cb_w        = (const float*)d_in[8];
    const float* cb_b        = (const float*)d_in[9];
    const int*   label       = (const int*)d_in[10];
    float* out = (float*)d_out;

    int eql_blocks = (EQL_W0 + 2 * EQL_W1 + 7) / 8;
    eqlin_all_kernel<<<eql_blocks, 256>>>(style, class_style, mod_w, mod_b,
                                          cw_w, cw_b, cb_w, cb_b);

    uprep_kernel<<<(CO_N * CI_N + 255) / 256, 256>>>(weight);
    vprep_kernel<<<BB * 256, 256>>>(input);

    wgemm_kernel<<<16 * 8 * 32, 256>>>();

    fuse_kernel<<<BB * CO_N, 256>>>(label, out);
}

// round 10
// speedup vs baseline: 14.7349x; 1.0261x over previous
#include <cuda_runtime.h>
#include <cuda_fp16.h>
#include <cstdint>

// Problem constants
#define BB    8
#define CI_N  512
#define CO_N  512
#define HWN   4096
#define NCLS  35
#define SDIM  512
#define NT    8192              // total output tiles: 8 b * 32*32

// ---------------- scratch (device globals) ----------------
__device__ float g_s[BB * CI_N];
__device__ float g_cwT[CO_N * NCLS];
__device__ float g_cbT[CO_N * NCLS];
__device__ __half g_U[(size_t)16 * CO_N * CI_N];          // fragment-ordered Winograd weights
__device__ uint32_t g_V[(size_t)16 * (CI_N / 2) * NT];    // half2(ci even, ci odd)
__device__ __half g_Mh[(size_t)16 * CO_N * NT];           // GEMM results (fp16, 134MB)

// ---------------- helpers ----------------
__device__ __forceinline__ uint32_t smem_u32(const void* p) {
    uint32_t a;
    asm("{ .reg .u64 t; cvta.to.shared.u64 t, %1; cvt.u32.u64 %0, t; }" : "=r"(a) : "l"(p));
    return a;
}
__device__ __forceinline__ void cp_async16(uint32_t dst, const void* src) {
    asm volatile("cp.async.cg.shared.global [%0], [%1], 16;" :: "r"(dst), "l"(src) : "memory");
}
#define CP_COMMIT() asm volatile("cp.async.commit_group;" ::: "memory")
#define CP_WAIT(n)  asm volatile("cp.async.wait_group %0;" :: "n"(n) : "memory")

__device__ __forceinline__ void mma16(float* c, uint4 a, uint32_t b0, uint32_t b1) {
    asm volatile(
        "mma.sync.aligned.m16n8k16.row.col.f32.f16.f16.f32 "
        "{%0,%1,%2,%3}, {%4,%5,%6,%7}, {%8,%9}, {%0,%1,%2,%3};"
        : "+f"(c[0]), "+f"(c[1]), "+f"(c[2]), "+f"(c[3])
        : "r"(a.x), "r"(a.y), "r"(a.z), "r"(a.w), "r"(b0), "r"(b1));
}
__device__ __forceinline__ uint32_t pack_h2(float a, float b) {
    __half2 h = __floats2half2_rn(a, b);
    return *(uint32_t*)&h;
}

// ---------------- EqualLinear (all three jobs in one launch) ----------------
#define EQL_W0 4096
#define EQL_W1 17920
__global__ void eqlin_all_kernel(const float* __restrict__ style,
                                 const float* __restrict__ class_style,
                                 const float* __restrict__ mod_w, const float* __restrict__ mod_b,
                                 const float* __restrict__ cw_w, const float* __restrict__ cw_b,
                                 const float* __restrict__ cb_w, const float* __restrict__ cb_b)
{
    int wg = (blockIdx.x * blockDim.x + threadIdx.x) >> 5;
    int lane = threadIdx.x & 31;
    const float *X, *W, *bias;
    float* dst;
    int i, j, sj, si;
    if (wg < EQL_W0) {
        i = wg >> 9; j = wg & 511;
        X = style; W = mod_w; bias = mod_b; dst = g_s; sj = 1; si = 512;
    } else if (wg < EQL_W0 + EQL_W1) {
        int r = wg - EQL_W0;
        i = r / 512; j = r & 511;
        X = class_style; W = cw_w; bias = cw_b; dst = g_cwT; sj = NCLS; si = 1;
    } else if (wg < EQL_W0 + 2 * EQL_W1) {
        int r = wg - EQL_W0 - EQL_W1;
        i = r / 512; j = r & 511;
        X = class_style; W = cb_w; bias = cb_b; dst = g_cbT; sj = NCLS; si = 1;
    } else return;

    const float4* x4 = (const float4*)(X + (size_t)i * SDIM);
    const float4* w4 = (const float4*)(W + (size_t)j * SDIM);
    float acc = 0.f;
#pragma unroll
    for (int q = 0; q < 4; q++) {
        float4 a = x4[lane + q * 32], b = w4[lane + q * 32];
        acc += a.x * b.x + a.y * b.y + a.z * b.z + a.w * b.w;
    }
#pragma unroll
    for (int o = 16; o > 0; o >>= 1) acc += __shfl_xor_sync(0xffffffffu, acc, o);
    if (lane == 0)
        dst[j * sj + i * si] = acc * 0.04419417382415922f + bias[j];
}

// ---------------- U-prep: U = G g G^T per (co,ci), fragment-ordered fp16 ----------------
__global__ void uprep_kernel(const float* __restrict__ w)
{
    int idx = blockIdx.x * 256 + threadIdx.x;      // co*512 + ci
    if (idx >= CO_N * CI_N) return;
    int co = idx >> 9, ci = idx & 511;
    const float* gp = w + (size_t)idx * 9;
    float g0[3] = {gp[0], gp[1], gp[2]};
    float g1[3] = {gp[3], gp[4], gp[5]};
    float g2[3] = {gp[6], gp[7], gp[8]};
    float T[4][3], U[4][4];
#pragma unroll
    for (int c = 0; c < 3; c++) {
        T[0][c] = g0[c];
        T[1][c] = 0.5f * (g0[c] + g1[c] + g2[c]);
        T[2][c] = 0.5f * (g0[c] - g1[c] + g2[c]);
        T[3][c] = g2[c];
    }
#pragma unroll
    for (int r = 0; r < 4; r++) {
        U[r][0] = T[r][0];
        U[r][1] = 0.5f * (T[r][0] + T[r][1] + T[r][2]);
        U[r][2] = 0.5f * (T[r][0] - T[r][1] + T[r][2]);
        U[r][3] = T[r][2];
    }
    int cob = co >> 6;
    int c16 = ci >> 4;
    int mt = (co >> 4) & 3;
    int gg = co & 7;
    int j1 = (co >> 3) & 1;
    int t = (ci >> 1) & 3;
    int j0 = ci & 1;
    int j2 = (ci >> 3) & 1;
    int lane = (gg << 2) | t;
    int j = j0 | (j1 << 1) | (j2 << 2);
#pragma unroll
    for (int e = 0; e < 16; e++) {
        size_t addr = ((((size_t)e * 8 + cob) * 32 + c16) * 4 + mt) * 256 + lane * 8 + j;
        g_U[addr] = __float2half_rn(U[e >> 2][e & 3]);
    }
}

// ---------------- V-prep: V = B^T d B per 4x4 patch, style-scaled, half2 packed ----------------
__global__ void __launch_bounds__(256) vprep_kernel(const float* __restrict__ x)
{
    __shared__ float xs[2 * 66 * 66];
    const int tid = threadIdx.x;
    const int b = blockIdx.x >> 8;
    const int ci2 = blockIdx.x & 255;

    for (int i = tid; i < 2 * 66 * 66; i += 256) xs[i] = 0.f;
    __syncthreads();

    const float s0 = g_s[b * CI_N + 2 * ci2];
    const float s1 = g_s[b * CI_N + 2 * ci2 + 1];
    const float* x0 = x + ((size_t)b * CI_N + 2 * ci2) * HWN;
    const float* x1 = x0 + HWN;
    for (int i = tid; i < HWN; i += 256) {
        int r = i >> 6, c = i & 63;
        xs[(r + 1) * 66 + (c + 1)] = x0[i] * s0;
        xs[66 * 66 + (r + 1) * 66 + (c + 1)] = x1[i] * s1;
    }
    __syncthreads();

#pragma unroll 1
    for (int rep = 0; rep < 4; rep++) {
        int tpos = tid + rep * 256;
        int ty = tpos >> 5, tx = tpos & 31;
        float V2[2][4][4];
#pragma unroll
        for (int cin = 0; cin < 2; cin++) {
            const float* base = xs + cin * (66 * 66) + (2 * ty) * 66 + 2 * tx;
            float p[4][4];
#pragma unroll
            for (int r = 0; r < 4; r++)
#pragma unroll
                for (int c = 0; c < 4; c++) p[r][c] = base[r * 66 + c];
            float t1[4][4];
#pragma unroll
            for (int c = 0; c < 4; c++) {
                t1[0][c] = p[0][c] - p[2][c];
                t1[1][c] = p[1][c] + p[2][c];
                t1[2][c] = p[2][c] - p[1][c];
                t1[3][c] = p[1][c] - p[3][c];
            }
#pragma unroll
            for (int r = 0; r < 4; r++) {
                V2[cin][r][0] = t1[r][0] - t1[r][2];
                V2[cin][r][1] = t1[r][1] + t1[r][2];
                V2[cin][r][2] = t1[r][2] - t1[r][1];
                V2[cin][r][3] = t1[r][1] - t1[r][3];
            }
        }
        size_t n = (size_t)b * 1024 + tpos;
#pragma unroll
        for (int e = 0; e < 16; e++) {
            g_V[((size_t)e * 256 + ci2) * NT + n] =
                pack_h2(V2[0][e >> 2][e & 3], V2[1][e >> 2][e & 3]);
        }
    }
}

// ---------------- GEMM: M[e] = U[e] @ V[e]  (64co x 256n CTA tile) ----------------
// 4-stage cp.async pipeline, k32 chunks (2 mma k-steps per chunk), 1 sync/iter
#define BPITCH 264   // uint32 row pitch (264 % 32 == 8 -> conflict-free frag reads)
#define ASTG   4096                       // A stage bytes (2 x k16 fragment sets)
#define BSTG   (16 * BPITCH * 4)          // B stage bytes (16 half2 rows) = 16896
#define NSTAGE 4
#define WG_SMEM (NSTAGE * (ASTG + BSTG))  // 83968 B

// stage k32 chunk cc into stage slot s
__device__ __forceinline__ void gstage(uint32_t ab, uint32_t bb, int e, int cob,
                                       int nb, int cc, int tid)
{
    const __half* asrc = g_U + (((size_t)e * 8 + cob) * 32 + 2 * cc) * 1024;
    cp_async16(ab + tid * 16, asrc + (size_t)tid * 8);
    const uint32_t* bsrc = g_V + ((size_t)e * 256 + cc * 16) * NT + nb * 256;
#pragma unroll
    for (int k = 0; k < 4; k++) {
        int idx = tid + k * 256;
        int r = idx >> 6, q = idx & 63;
        cp_async16(bb + (r * BPITCH + q * 4) * 4, bsrc + (size_t)r * NT + q * 4);
    }
}

__global__ void __launch_bounds__(256, 2) wgemm_kernel()
{
    extern __shared__ __align__(16) char dsm[];

    const int tid = threadIdx.x;
    const int bx = blockIdx.x;
    // cob fastest: consecutive CTAs share the same B (V) tiles -> L2 hits
    const int cob = bx & 7, nb = (bx >> 3) & 31, e = bx >> 8;
    const int wid = tid >> 5, lane = tid & 31;
    const int wco = wid & 1, wn = wid >> 1;
    const int g = lane >> 2, t = lane & 3;

    const uint32_t abase = smem_u32(dsm);
    const uint32_t bbase = abase + NSTAGE * ASTG;

    float C[2][8][4];
#pragma unroll
    for (int m = 0; m < 2; m++)
#pragma unroll
        for (int tn = 0; tn < 8; tn++)
#pragma unroll
            for (int j = 0; j < 4; j++) C[m][tn][j] = 0.f;

    // prologue: prefetch chunks 0,1,2
#pragma unroll
    for (int s = 0; s < 3; s++) {
        gstage(abase + s * ASTG, bbase + s * BSTG, e, cob, nb, s, tid);
        CP_COMMIT();
    }

#pragma unroll 1
    for (int cc = 0; cc < 16; cc++) {
        const int s = cc & 3;
        CP_WAIT(2);
        __syncthreads();
        // prefetch chunk cc+3 into slot (cc+3)&3 == (cc-1)&3 (freed by the sync above)
        if (cc + 3 < 16)
            gstage(abase + ((cc + 3) & 3) * ASTG, bbase + ((cc + 3) & 3) * BSTG,
                   e, cob, nb, cc + 3, tid);
        CP_COMMIT();

        const uint4* abuf = (const uint4*)(dsm + s * ASTG);
        const uint32_t* bbuf = (const uint32_t*)(dsm + NSTAGE * ASTG + s * BSTG);
#pragma unroll
        for (int ks = 0; ks < 2; ks++) {
            uint4 A0 = abuf[ks * 128 + (2 * wco + 0) * 32 + lane];
            uint4 A1 = abuf[ks * 128 + (2 * wco + 1) * 32 + lane];
            const uint32_t* br0 = bbuf + (ks * 8 + t) * BPITCH + wn * 64 + g;
            const uint32_t* br1 = bbuf + (ks * 8 + t + 4) * BPITCH + wn * 64 + g;
#pragma unroll
            for (int tn = 0; tn < 8; tn++) {
                uint32_t b0 = br0[tn * 8];
                uint32_t b1 = br1[tn * 8];
                mma16(C[0][tn], A0, b0, b1);
                mma16(C[1][tn], A1, b0, b1);
            }
        }
    }

    // epilogue: write M fp16
#pragma unroll
    for (int m = 0; m < 2; m++) {
        int co = cob * 64 + wco * 32 + m * 16 + g;
        __half* base = g_Mh + ((size_t)e * 512 + co) * NT + nb * 256 + wn * 64;
#pragma unroll
        for (int tn = 0; tn < 8; tn++) {
            int col = tn * 8 + 2 * t;
            *(uint32_t*)(base + col) = pack_h2(C[m][tn][0], C[m][tn][1]);
            *(uint32_t*)(base + 8 * NT + col) = pack_h2(C[m][tn][2], C[m][tn][3]);
        }
    }
}

// ---------------- fused: output transform + instance norm + CLADE apply ----------------
__global__ void __launch_bounds__(256) fuse_kernel(const int* __restrict__ label,
                                                   float* __restrict__ out)
{
    const int bc = blockIdx.x;            // b*512 + co
    const int b = bc >> 9, co = bc & 511;
    const int t = threadIdx.x;

    float Y[4][4];
    float s1 = 0.f, s2 = 0.f;

#pragma unroll
    for (int k = 0; k < 4; k++) {
        const size_t n = (size_t)b * 1024 + t + k * 256;
        float m[16];
#pragma unroll
        for (int e = 0; e < 16; e++)
            m[e] = __half2float(g_Mh[((size_t)e * 512 + co) * NT + n]);

        float t0[4], t1[4];
#pragma unroll
        for (int c = 0; c < 4; c++) {
            t0[c] = m[0 + c] + m[4 + c] + m[8 + c];
            t1[c] = m[4 + c] - m[8 + c] - m[12 + c];
        }
        float y00 = t0[0] + t0[1] + t0[2];
        float y01 = t0[1] - t0[2] - t0[3];
        float y10 = t1[0] + t1[1] + t1[2];
        float y11 = t1[1] - t1[2] - t1[3];
        Y[k][0] = y00; Y[k][1] = y01; Y[k][2] = y10; Y[k][3] = y11;
        s1 += (y00 + y01) + (y10 + y11);
        s2 += y00 * y00 + y01 * y01 + y10 * y10 + y11 * y11;
    }

#pragma unroll
    for (int o = 16; o > 0; o >>= 1) {
        s1 += __shfl_xor_sync(0xffffffffu, s1, o);
        s2 += __shfl_xor_sync(0xffffffffu, s2, o);
    }
    __shared__ float r1[8], r2[8];
    __shared__ float sh_mu, sh_rs;
    if ((t & 31) == 0) { r1[t >> 5] = s1; r2[t >> 5] = s2; }
    __syncthreads();
    if (t < 8) {
        s1 = r1[t]; s2 = r2[t];
#pragma unroll
        for (int o = 4; o > 0; o >>= 1) {
            s1 += __shfl_xor_sync(0xffu, s1, o);
            s2 += __shfl_xor_sync(0xffu, s2, o);
        }
        if (t == 0) {
            float mu = s1 * (1.f / 4096.f);
            float var = s2 * (1.f / 4096.f) - mu * mu;
            sh_mu = mu;
            sh_rs = rsqrtf(var + 1e-5f);
        }
    }
    __syncthreads();

    const float mu = sh_mu, rs = sh_rs;
    const float* cw = g_cwT + co * NCLS;
    const float* cb = g_cbT + co * NCLS;
    const int* lb = label + (size_t)b * HWN;
    float* ob = out + (size_t)bc * HWN;

#pragma unroll
    for (int k = 0; k < 4; k++) {
        int tpos = t + k * 256;
        int ty = tpos >> 5, tx = tpos & 31;
        int off = (2 * ty) * 64 + 2 * tx;
        int2 l0 = *(const int2*)(lb + off);
        int2 l1 = *(const int2*)(lb + off + 64);
        float2 o0, o1;
        o0.x = (Y[k][0] - mu) * rs * cw[l0.x] + cb[l0.x];
        o0.y = (Y[k][1] - mu) * rs * cw[l0.y] + cb[l0.y];
        o1.x = (Y[k][2] - mu) * rs * cw[l1.x] + cb[l1.x];
        o1.y = (Y[k][3] - mu) * rs * cw[l1.y] + cb[l1.y];
        *(float2*)(ob + off) = o0;
        *(float2*)(ob + off + 64) = o1;
    }
}

// ---------------- launch ----------------
extern "C" void kernel_launch(void* const* d_in, const int* in_sizes, int n_in,
                              void* d_out, int out_size)
{
    const float* input       = (const float*)d_in[0];
    const float* style       = (const float*)d_in[1];
    const float* class_style = (const float*)d_in[2];
    const float* weight      = (const float*)d_in[3];
    const float* mod_w       = (const float*)d_in[4];
    const float* mod_b       = (const float*)d_in[5];
    const float* cw_w        = (const float*)d_in[6];
    const float* cw_b        = (const float*)d_in[7];
    const float* cb_w        = (const float*)d_in[8];
    const float* cb_b        = (const float*)d_in[9];
    const int*   label       = (const int*)d_in[10];
    float* out = (float*)d_out;

    cudaFuncSetAttribute(wgemm_kernel,
                         cudaFuncAttributeMaxDynamicSharedMemorySize, WG_SMEM);

    int eql_blocks = (EQL_W0 + 2 * EQL_W1 + 7) / 8;
    eqlin_all_kernel<<<eql_blocks, 256>>>(style, class_style, mod_w, mod_b,
                                          cw_w, cw_b, cb_w, cb_b);

    uprep_kernel<<<(CO_N * CI_N + 255) / 256, 256>>>(weight);
    vprep_kernel<<<BB * 256, 256>>>(input);

    wgemm_kernel<<<16 * 8 * 32, 256, WG_SMEM>>>();

    fuse_kernel<<<BB * CO_N, 256>>>(label, out);
}